// round 9
// baseline (speedup 1.0000x reference)
#include <cuda_runtime.h>
#include <cuda_fp16.h>
#include <cstdint>

#define Fdim 128
#define ET2  256              // rows per CTA tile (MMA M)
#define MAXN 50000

// ---------------- scratch (static device arrays; allocation-free) ----------
__device__ float g_mi[(size_t)MAXN * 128];
__device__ float g_dx4[(size_t)MAXN * 4];
__device__ __align__(16) __half g_nodeh[(size_t)MAXN * 128];   // fp16 node table
__device__ __align__(16) float g_P[(size_t)MAXN * 128];        // node @ We1_top + be1
__device__ __align__(16) float g_Q[(size_t)MAXN * 128];        // node @ We1_bot
// swizzled fp16 weight chunk images: rows=n(128), kc(64)
__device__ __align__(16) __half gB1[4][8192];   // We1 (k chunks 0..3)
__device__ __align__(16) __half gB2[2][8192];   // We2
__device__ __align__(16) __half gH1[4][8192];   // Wh1
__device__ __align__(16) __half gH2[2][8192];   // Wh2

#define BCH 16384            /* bytes per B chunk */

// ---------------- PTX helpers ----------------------------------------------
__device__ __forceinline__ uint32_t smem_u32(const void* p) {
    uint32_t a;
    asm("{ .reg .u64 t; cvta.to.shared.u64 t, %1; cvt.u32.u64 %0, t; }" : "=r"(a) : "l"(p));
    return a;
}

#define LDSM4(r0, r1, r2, r3, addr) \
    asm volatile("ldmatrix.sync.aligned.m8n8.x4.shared.b16 {%0,%1,%2,%3}, [%4];" \
                 : "=r"(r0), "=r"(r1), "=r"(r2), "=r"(r3) : "r"(addr))

#define MMA16816(cp, a0, a1, a2, a3, b0, b1) \
    asm volatile("mma.sync.aligned.m16n8k16.row.col.f32.f16.f16.f32 " \
                 "{%0,%1,%2,%3},{%4,%5,%6,%7},{%8,%9},{%0,%1,%2,%3};" \
                 : "+f"((cp)[0]), "+f"((cp)[1]), "+f"((cp)[2]), "+f"((cp)[3]) \
                 : "r"(a0), "r"(a1), "r"(a2), "r"(a3), "r"(b0), "r"(b1))

#define MB_INIT(mb, c) asm volatile("mbarrier.init.shared.b64 [%0], %1;" :: "r"(mb), "r"(c) : "memory")
#define MB_EXPECT(mb, b) asm volatile("mbarrier.arrive.expect_tx.shared.b64 _, [%0], %1;" :: "r"(mb), "r"(b) : "memory")
#define BULK_G2S(dst, src, bytes, mb) \
    asm volatile("cp.async.bulk.shared::cluster.global.mbarrier::complete_tx::bytes [%0], [%1], %2, [%3];" \
                 :: "r"(dst), "l"(src), "r"(bytes), "r"(mb) : "memory")

#define CPA16(dst, src, n) \
    asm volatile("cp.async.cg.shared.global [%0], [%1], 16, %2;" :: "r"(dst), "l"(src), "r"(n) : "memory")
#define CPA_COMMIT() asm volatile("cp.async.commit_group;" ::: "memory")
#define CPA_WAIT0()  asm volatile("cp.async.wait_group 0;" ::: "memory")

__device__ __forceinline__ void mb_wait(uint32_t mb, uint32_t parity) {
    uint32_t done;
    asm volatile("{ .reg .pred p; mbarrier.try_wait.parity.acquire.cta.shared::cta.b64 p, [%1], %2; selp.b32 %0, 1, 0, p; }"
                 : "=r"(done) : "r"(mb), "r"(parity) : "memory");
    if (!done) {
        asm volatile("{ .reg .pred P1;\nW%=:\n mbarrier.try_wait.parity.acquire.cta.shared::cta.b64 P1, [%0], %1, 0x989680;\n @P1 bra.uni D%=;\n bra.uni W%=;\nD%=:\n}"
                     :: "r"(mb), "r"(parity) : "memory");
    }
}

__device__ __forceinline__ void red2(float* p, float x, float y) {
    asm volatile("red.global.add.v2.f32 [%0], {%1,%2};" :: "l"(p), "f"(x), "f"(y) : "memory");
}
__device__ __forceinline__ void red4(float* p, float4 v) {
    asm volatile("red.global.add.v4.f32 [%0], {%1,%2,%3,%4};"
                 :: "l"(p), "f"(v.x), "f"(v.y), "f"(v.z), "f"(v.w) : "memory");
}

__device__ __forceinline__ uint32_t packhf2(float a, float b) {
    uint32_t r;
    asm("cvt.rn.f16x2.f32 %0, %1, %2;" : "=r"(r) : "f"(b), "f"(a));
    return r;
}

// swizzled element offset within a [row][kc] tile, 64 fp16 per row (128 B)
__host__ __device__ __forceinline__ int swoff(int n, int kc) {
    return n * 64 + ((((kc >> 3) ^ (n & 7)) << 3) | (kc & 7));
}

// ---------------- prep: swizzled fp16 weight chunk images -------------------
__global__ void prep_kernel(const float* __restrict__ We1, const float* __restrict__ We2,
                            const float* __restrict__ Wh1, const float* __restrict__ Wh2)
{
    int id = blockIdx.x * blockDim.x + threadIdx.x;
    if (id < 32768) {
        int c = id >> 13, rem = id & 8191, n = rem >> 6, kc = rem & 63;
        gB1[c][swoff(n, kc)] = __float2half_rn(We1[(size_t)(c * 64 + kc) * 128 + n]);
    } else if (id < 49152) {
        int id2 = id - 32768;
        int c = id2 >> 13, rem = id2 & 8191, n = rem >> 6, kc = rem & 63;
        gB2[c][swoff(n, kc)] = __float2half_rn(We2[(size_t)(c * 64 + kc) * 128 + n]);
    } else if (id < 81920) {
        int id2 = id - 49152;
        int c = id2 >> 13, rem = id2 & 8191, n = rem >> 6, kc = rem & 63;
        gH1[c][swoff(n, kc)] = __float2half_rn(Wh1[(size_t)(c * 64 + kc) * 128 + n]);
    } else if (id < 98304) {
        int id2 = id - 81920;
        int c = id2 >> 13, rem = id2 & 8191, n = rem >> 6, kc = rem & 63;
        gH2[c][swoff(n, kc)] = __float2half_rn(Wh2[(size_t)(c * 64 + kc) * 128 + n]);
    }
}

// ---------------- zero scratch + convert node table to fp16 -----------------
__global__ void zero_kernel(const float* __restrict__ node, int n_mi, int n_dx)
{
    int i = blockIdx.x * blockDim.x + threadIdx.x;
    if (i < n_mi) {
        g_mi[i] = 0.0f;
        g_nodeh[i] = __float2half_rn(node[i]);
    }
    if (i < n_dx) g_dx4[i] = 0.0f;
}

// ---------------- shared MMA tile machinery ---------------------------------
#define SO_A0   0
#define SO_A1   32768
#define SO_B0   65536
#define SO_B1   81920
// edge extras
#define SO_DS   98304      /* float4[256] */
#define SO_W    102400     /* float[256] */
#define SO_DST  103424     /* int[256] */
#define SO_WX   104448
#define SO_BE2  104960
#define SO_W256 105472
#define SO_MB   105984
#define EDGE_SMEM 106016
// pq extras
#define PQ_BE1  98304
#define PQ_MB   98816
#define PQ_SMEM 98848
// node extras
#define NO_BH1  98304
#define NO_BH2  98816
#define NO_MB   99328
#define NODE_SMEM 99360

// ---------------- PQ precompute: P = node@W_top + be1 ; Q = node@W_bot ------
__global__ __launch_bounds__(512, 1)
void pq_kernel(const float* __restrict__ be1, int N)
{
    extern __shared__ char sm[];
    const uint32_t sbase = smem_u32(sm);
    float* sBe1 = (float*)(sm + PQ_BE1);

    const int t    = threadIdx.x;
    const int wid  = t >> 5;
    const int lane = t & 31;
    const int n0   = blockIdx.x * ET2;

    const uint32_t mb0 = sbase + PQ_MB;
    const uint32_t mb1 = sbase + PQ_MB + 8;

    if (t == 0) { MB_INIT(mb0, 1); MB_INIT(mb1, 1); }
    if (t < 128) sBe1[t] = be1[t];
    __syncthreads();

    if (t == 0) {
        MB_EXPECT(mb0, BCH);
        BULK_G2S(sbase + SO_B0, (const void*)gB1[0], BCH, mb0);
        MB_EXPECT(mb1, BCH);
        BULK_G2S(sbase + SO_B1, (const void*)gB1[1], BCH, mb1);
    }

    const int grow  = t >> 1;
    const int ghalf = t & 1;
    const int grnode = n0 + grow;
    const bool gvalid = grnode < N;
    const int grclamp = gvalid ? grnode : 0;
    const uint32_t g_rowoff = (uint32_t)grow * 128;
    const int      g_rx     = grow & 7;
    const uint32_t g_nsz    = gvalid ? 16u : 0u;

    // stage node fp16 chunk c (k = c*64..+63) into A buffer
    auto stageN = [&](int c, uint32_t abo) {
        const __half* rp = g_nodeh + (size_t)grclamp * 128 + c * 64 + ghalf * 32;
        #pragma unroll
        for (int u = 0; u < 4; ++u) {
            uint32_t dst = sbase + abo + g_rowoff + (uint32_t)(((ghalf * 4 + u) ^ g_rx) << 4);
            CPA16(dst, rp + u * 8, g_nsz);
        }
        CPA_COMMIT();
    };

    const int seg = lane >> 3;
    const int lnx = lane & 7;
    const int sA_r = seg & 1;
    const int sA_g = (seg >> 1) & 1;
    const int sB_r = (seg >> 1) & 1;
    const int sB_g = seg & 1;
    const uint32_t a_rowoff = (uint32_t)(wid * 16 + lnx + sA_r * 8) * 128;
    const uint32_t b_rowoff = (uint32_t)(lnx + sB_r * 8) * 128;

    auto doChunk = [&](uint32_t Ab, uint32_t Bb, float* cc) {
        #pragma unroll
        for (int ks = 0; ks < 4; ++ks) {
            uint32_t ag = (uint32_t)(((2 * ks) | sA_g) ^ lnx) << 4;
            uint32_t bg = (uint32_t)(((2 * ks) | sB_g) ^ lnx) << 4;
            uint32_t a0,a1,a2,a3;
            LDSM4(a0,a1,a2,a3, sbase + Ab + a_rowoff + ag);
            #pragma unroll
            for (int jb = 0; jb < 8; ++jb) {
                uint32_t baddr = sbase + Bb + b_rowoff + (uint32_t)(jb * 2048) + bg;
                uint32_t b0,b1,b2,b3;
                LDSM4(b0,b1,b2,b3, baddr);
                float* cp0 = cc + 8 * jb;
                float* cp1 = cc + 8 * jb + 4;
                MMA16816(cp0, a0,a1,a2,a3, b0,b1);
                MMA16816(cp1, a0,a1,a2,a3, b2,b3);
            }
        }
    };

    float cc[64];
    #pragma unroll
    for (int i = 0; i < 64; ++i) cc[i] = 0.0f;

    stageN(0, SO_A0);
    stageN(1, SO_A1);
    CPA_WAIT0();
    __syncthreads();

    // P pass: A0@gB1[0] + A1@gB1[1]
    mb_wait(mb0, 0);
    doChunk(SO_A0, SO_B0, cc);
    __syncthreads();
    if (t == 0) { MB_EXPECT(mb0, BCH); BULK_G2S(sbase + SO_B0, (const void*)gB1[2], BCH, mb0); }
    mb_wait(mb1, 0);
    doChunk(SO_A1, SO_B1, cc);
    __syncthreads();
    if (t == 0) { MB_EXPECT(mb1, BCH); BULK_G2S(sbase + SO_B1, (const void*)gB1[3], BCH, mb1); }

    const int r0 = wid * 16 + (lane >> 2);
    const int q  = lane & 3;
    const int row0 = n0 + r0;
    const int row1 = row0 + 8;

    #pragma unroll
    for (int f = 0; f < 16; ++f) {
        int col = 8 * f + 2 * q;
        float2 b = *(float2*)(sBe1 + col);
        if (row0 < N) {
            float2 v; v.x = cc[4*f+0] + b.x; v.y = cc[4*f+1] + b.y;
            *(float2*)(g_P + (size_t)row0 * 128 + col) = v;
        }
        if (row1 < N) {
            float2 v; v.x = cc[4*f+2] + b.x; v.y = cc[4*f+3] + b.y;
            *(float2*)(g_P + (size_t)row1 * 128 + col) = v;
        }
    }

    // Q pass: A0@gB1[2] + A1@gB1[3]
    #pragma unroll
    for (int i = 0; i < 64; ++i) cc[i] = 0.0f;
    mb_wait(mb0, 1);
    doChunk(SO_A0, SO_B0, cc);
    mb_wait(mb1, 1);
    doChunk(SO_A1, SO_B1, cc);

    #pragma unroll
    for (int f = 0; f < 16; ++f) {
        int col = 8 * f + 2 * q;
        if (row0 < N) {
            float2 v; v.x = cc[4*f+0]; v.y = cc[4*f+1];
            *(float2*)(g_Q + (size_t)row0 * 128 + col) = v;
        }
        if (row1 < N) {
            float2 v; v.x = cc[4*f+2]; v.y = cc[4*f+3];
            *(float2*)(g_Q + (size_t)row1 * 128 + col) = v;
        }
    }
}

// ---------------- edge kernel: hidden = relu(P[dst]+Q[src]+sq*w256) @ We2 ---
__global__ __launch_bounds__(512, 1)
void edge_kernel(const float* __restrict__ coord,
                 const int*   __restrict__ ei,
                 const float* __restrict__ We1,
                 const float* __restrict__ be2,
                 const float* __restrict__ Wx,
                 const float* __restrict__ bxp,
                 int E)
{
    extern __shared__ char sm[];
    const uint32_t sbase = smem_u32(sm);

    float4* sDS  = (float4*)(sm + SO_DS);
    float*  sW   = (float*)(sm + SO_W);
    int*    sDst = (int*)(sm + SO_DST);
    float*  sWx  = (float*)(sm + SO_WX);
    float*  sBe2 = (float*)(sm + SO_BE2);
    float*  sW256= (float*)(sm + SO_W256);

    const int t    = threadIdx.x;
    const int wid  = t >> 5;
    const int lane = t & 31;
    const int e0   = blockIdx.x * ET2;
    const float bx = bxp[0];

    const uint32_t mb0 = sbase + SO_MB;
    const uint32_t mb1 = sbase + SO_MB + 8;

    if (t == 0) { MB_INIT(mb0, 1); MB_INIT(mb1, 1); }

    if (t < ET2) {
        int eg = e0 + t;
        float dx = 0.f, dy = 0.f, dz = 0.f;
        int di = -1;
        if (eg < E) {
            int si = ei[eg];
            di     = ei[E + eg];
            dx = coord[(size_t)di * 3 + 0] - coord[(size_t)si * 3 + 0];
            dy = coord[(size_t)di * 3 + 1] - coord[(size_t)si * 3 + 1];
            dz = coord[(size_t)di * 3 + 2] - coord[(size_t)si * 3 + 2];
        }
        sDS[t]  = make_float4(dx, dy, dz, dx * dx + dy * dy + dz * dz);
        sDst[t] = di;
    }
    if (t < 128) {
        sWx[t]  = Wx[t];
        sBe2[t] = be2[t];
        sW256[t]= We1[(size_t)256 * 128 + t];
    }
    __syncthreads();          // mbarriers + metadata + sW256 visible

    if (t == 0) {
        MB_EXPECT(mb0, BCH);
        BULK_G2S(sbase + SO_B0, (const void*)gB2[0], BCH, mb0);
        MB_EXPECT(mb1, BCH);
        BULK_G2S(sbase + SO_B1, (const void*)gB2[1], BCH, mb1);
    }

    // gather role: 2 threads per edge row
    const int grow  = t >> 1;
    const int ghalf = t & 1;
    int gsi = 0, gdi = 0;
    const bool gvalid = (e0 + grow) < E;
    if (gvalid) { gsi = ei[e0 + grow]; gdi = ei[E + e0 + grow]; }
    const uint32_t g_rowoff = (uint32_t)grow * 128;
    const int      g_rx     = grow & 7;

    // stage hidden chunk c: relu(P[dst]+Q[src]+sq*w256) -> fp16 swizzled
    auto stageH = [&](int c, uint32_t abo) {
        const int cb = c * 64 + ghalf * 32;
        const float* pp = g_P + (size_t)gdi * 128 + cb;
        const float* qq = g_Q + (size_t)gsi * 128 + cb;
        const float* ww = sW256 + cb;
        const float sq  = sDS[grow].w;
        #pragma unroll
        for (int u = 0; u < 4; ++u) {
            uint4 H;
            float4 p0 = *(const float4*)(pp + u * 8);
            float4 p1 = *(const float4*)(pp + u * 8 + 4);
            float4 q0 = *(const float4*)(qq + u * 8);
            float4 q1 = *(const float4*)(qq + u * 8 + 4);
            float4 w0 = *(const float4*)(ww + u * 8);
            float4 w1 = *(const float4*)(ww + u * 8 + 4);
            float v0 = fmaxf(fmaf(sq, w0.x, p0.x + q0.x), 0.0f);
            float v1 = fmaxf(fmaf(sq, w0.y, p0.y + q0.y), 0.0f);
            float v2 = fmaxf(fmaf(sq, w0.z, p0.z + q0.z), 0.0f);
            float v3 = fmaxf(fmaf(sq, w0.w, p0.w + q0.w), 0.0f);
            float v4 = fmaxf(fmaf(sq, w1.x, p1.x + q1.x), 0.0f);
            float v5 = fmaxf(fmaf(sq, w1.y, p1.y + q1.y), 0.0f);
            float v6 = fmaxf(fmaf(sq, w1.z, p1.z + q1.z), 0.0f);
            float v7 = fmaxf(fmaf(sq, w1.w, p1.w + q1.w), 0.0f);
            H.x = packhf2(v0, v1);
            H.y = packhf2(v2, v3);
            H.z = packhf2(v4, v5);
            H.w = packhf2(v6, v7);
            uint32_t off = g_rowoff + (uint32_t)(((ghalf * 4 + u) ^ g_rx) << 4);
            *(uint4*)(sm + abo + off) = H;
        }
    };

    const int seg = lane >> 3;
    const int lnx = lane & 7;
    const int sA_r = seg & 1;
    const int sA_g = (seg >> 1) & 1;
    const int sB_r = (seg >> 1) & 1;
    const int sB_g = seg & 1;
    const uint32_t a_rowoff = (uint32_t)(wid * 16 + lnx + sA_r * 8) * 128;
    const uint32_t b_rowoff = (uint32_t)(lnx + sB_r * 8) * 128;

    auto doChunk = [&](uint32_t Ab, uint32_t Bb, float* cc) {
        #pragma unroll
        for (int ks = 0; ks < 4; ++ks) {
            uint32_t ag = (uint32_t)(((2 * ks) | sA_g) ^ lnx) << 4;
            uint32_t bg = (uint32_t)(((2 * ks) | sB_g) ^ lnx) << 4;
            uint32_t a0,a1,a2,a3;
            LDSM4(a0,a1,a2,a3, sbase + Ab + a_rowoff + ag);
            #pragma unroll
            for (int jb = 0; jb < 8; ++jb) {
                uint32_t baddr = sbase + Bb + b_rowoff + (uint32_t)(jb * 2048) + bg;
                uint32_t b0,b1,b2,b3;
                LDSM4(b0,b1,b2,b3, baddr);
                float* cp0 = cc + 8 * jb;
                float* cp1 = cc + 8 * jb + 4;
                MMA16816(cp0, a0,a1,a2,a3, b0,b1);
                MMA16816(cp1, a0,a1,a2,a3, b2,b3);
            }
        }
    };

    float c2[64];
    #pragma unroll
    for (int i = 0; i < 64; ++i) c2[i] = 0.0f;

    stageH(0, SO_A0);
    __syncthreads();
    stageH(1, SO_A1);          // writes A1 while chunk-0 MMA can proceed

    mb_wait(mb0, 0);
    doChunk(SO_A0, SO_B0, c2);
    __syncthreads();           // A1 fully staged, everyone done with chunk 0

    mb_wait(mb1, 0);
    doChunk(SO_A1, SO_B1, c2);

    // ============ epilogue: bias, scalar head, register-direct scatter ======
    const int r0 = wid * 16 + (lane >> 2);
    const int q  = lane & 3;
    const int dst0 = sDst[r0];
    const int dst1 = sDst[r0 + 8];
    float w0 = 0.0f, w1 = 0.0f;
    #pragma unroll
    for (int f = 0; f < 16; ++f) {
        int col = 8 * f + 2 * q;
        float2 b  = *(float2*)(sBe2 + col);
        float2 wx = *(float2*)(sWx + col);
        float v0 = c2[4*f+0] + b.x;
        float v1 = c2[4*f+1] + b.y;
        float v2 = c2[4*f+2] + b.x;
        float v3 = c2[4*f+3] + b.y;
        w0 = fmaf(v0, wx.x, fmaf(v1, wx.y, w0));
        w1 = fmaf(v2, wx.x, fmaf(v3, wx.y, w1));
        if (dst0 >= 0) red2(g_mi + (size_t)dst0 * 128 + col, v0, v1);
        if (dst1 >= 0) red2(g_mi + (size_t)dst1 * 128 + col, v2, v3);
    }
    w0 += __shfl_xor_sync(0xffffffffu, w0, 1);
    w0 += __shfl_xor_sync(0xffffffffu, w0, 2);
    w1 += __shfl_xor_sync(0xffffffffu, w1, 1);
    w1 += __shfl_xor_sync(0xffffffffu, w1, 2);
    if (q == 0) {
        sW[r0]     = w0 + bx;
        sW[r0 + 8] = w1 + bx;
    }
    __syncthreads();

    if (t < ET2) {
        int di = sDst[t];
        if (di >= 0) {
            float w = sW[t];
            float4 ds = sDS[t];
            red4(g_dx4 + (size_t)di * 4, make_float4(ds.x * w, ds.y * w, ds.z * w, 0.0f));
        }
    }
}

// ---------------- node kernel: fp16 MMA [node|m_i] @ Wh1 -> relu -> @ Wh2 ---
__global__ __launch_bounds__(512, 1)
void node_kernel(const float* __restrict__ bh1,
                 const float* __restrict__ bh2,
                 float* __restrict__ outH,
                 int N)
{
    extern __shared__ char sm[];
    const uint32_t sbase = smem_u32(sm);

    float* sBh1 = (float*)(sm + NO_BH1);
    float* sBh2 = (float*)(sm + NO_BH2);

    const int t    = threadIdx.x;
    const int wid  = t >> 5;
    const int lane = t & 31;
    const int n0   = blockIdx.x * ET2;

    const uint32_t mb0 = sbase + NO_MB;
    const uint32_t mb1 = sbase + NO_MB + 8;

    if (t == 0) { MB_INIT(mb0, 1); MB_INIT(mb1, 1); }
    if (t < 128) {
        sBh1[t] = bh1[t];
        sBh2[t] = bh2[t];
    }
    __syncthreads();

    if (t == 0) {
        MB_EXPECT(mb0, BCH);
        BULK_G2S(sbase + SO_B0, (const void*)gH1[0], BCH, mb0);
        MB_EXPECT(mb1, BCH);
        BULK_G2S(sbase + SO_B1, (const void*)gH1[1], BCH, mb1);
    }

    const int grow  = t >> 1;
    const int ghalf = t & 1;
    const int grnode = n0 + grow;
    const bool gvalid = grnode < N;
    const int grclamp = gvalid ? grnode : 0;
    const uint32_t g_rowoff = (uint32_t)grow * 128;
    const int      g_rx     = grow & 7;
    const uint32_t g_nsz    = gvalid ? 16u : 0u;

    auto stageN = [&](int c, uint32_t abo) {
        const __half* rp = g_nodeh + (size_t)grclamp * 128 + c * 64 + ghalf * 32;
        #pragma unroll
        for (int u = 0; u < 4; ++u) {
            uint32_t dst = sbase + abo + g_rowoff + (uint32_t)(((ghalf * 4 + u) ^ g_rx) << 4);
            CPA16(dst, rp + u * 8, g_nsz);
        }
        CPA_COMMIT();
    };
    auto stageM = [&](int c, uint32_t abo) {
        const float* rp = g_mi + (size_t)grclamp * 128 + (c - 2) * 64 + ghalf * 32;
        #pragma unroll
        for (int u = 0; u < 4; ++u) {
            uint4 H;
            if (gvalid) {
                float4 v0 = *(const float4*)(rp + u * 8);
                float4 v1 = *(const float4*)(rp + u * 8 + 4);
                H.x = packhf2(v0.x, v0.y);
                H.y = packhf2(v0.z, v0.w);
                H.z = packhf2(v1.x, v1.y);
                H.w = packhf2(v1.z, v1.w);
            } else {
                H = make_uint4(0u, 0u, 0u, 0u);
            }
            uint32_t off = g_rowoff + (uint32_t)(((ghalf * 4 + u) ^ g_rx) << 4);
            *(uint4*)(sm + abo + off) = H;
        }
    };

    const int seg = lane >> 3;
    const int lnx = lane & 7;
    const int sA_r = seg & 1;
    const int sA_g = (seg >> 1) & 1;
    const int sB_r = (seg >> 1) & 1;
    const int sB_g = seg & 1;
    const uint32_t a_rowoff = (uint32_t)(wid * 16 + lnx + sA_r * 8) * 128;
    const uint32_t b_rowoff = (uint32_t)(lnx + sB_r * 8) * 128;

    auto doChunk = [&](uint32_t Ab, uint32_t Bb, float* cc) {
        #pragma unroll
        for (int ks = 0; ks < 4; ++ks) {
            uint32_t ag = (uint32_t)(((2 * ks) | sA_g) ^ lnx) << 4;
            uint32_t bg = (uint32_t)(((2 * ks) | sB_g) ^ lnx) << 4;
            uint32_t a0,a1,a2,a3;
            LDSM4(a0,a1,a2,a3, sbase + Ab + a_rowoff + ag);
            #pragma unroll
            for (int jb = 0; jb < 8; ++jb) {
                uint32_t baddr = sbase + Bb + b_rowoff + (uint32_t)(jb * 2048) + bg;
                uint32_t b0,b1,b2,b3;
                LDSM4(b0,b1,b2,b3, baddr);
                float* cp0 = cc + 8 * jb;
                float* cp1 = cc + 8 * jb + 4;
                MMA16816(cp0, a0,a1,a2,a3, b0,b1);
                MMA16816(cp1, a0,a1,a2,a3, b2,b3);
            }
        }
    };

    float c1[64];
    #pragma unroll
    for (int i = 0; i < 64; ++i) c1[i] = 0.0f;

    stageN(0, SO_A0);
    CPA_WAIT0();
    __syncthreads();

    uint32_t ph0 = 0, ph1 = 0;

    #pragma unroll 1
    for (int c = 0; c < 4; ++c) {
        if (c & 1) { mb_wait(mb1, ph1); ph1 ^= 1; }
        else       { mb_wait(mb0, ph0); ph0 ^= 1; }

        if (c == 0)      stageN(1, SO_A1);
        else if (c == 1) stageM(2, SO_A0);
        else if (c == 2) stageM(3, SO_A1);

        doChunk((c & 1) ? SO_A1 : SO_A0, (c & 1) ? SO_B1 : SO_B0, c1);
        CPA_WAIT0();
        __syncthreads();

        if (t == 0) {
            const void* nsrc = (c == 0) ? (const void*)gH1[2]
                             : (c == 1) ? (const void*)gH1[3]
                             : (c == 2) ? (const void*)gH2[0]
                                        : (const void*)gH2[1];
            uint32_t dst = (c & 1) ? (sbase + SO_B1) : (sbase + SO_B0);
            uint32_t mb  = (c & 1) ? mb1 : mb0;
            MB_EXPECT(mb, BCH);
            BULK_G2S(dst, nsrc, BCH, mb);
        }
    }

    const int r0 = wid * 16 + (lane >> 2);
    const int q  = lane & 3;
    const uint32_t hrow0 = (uint32_t)r0 * 128;
    const int      hrx   = r0 & 7;
    #pragma unroll
    for (int f = 0; f < 16; ++f) {
        int col = 8 * f + 2 * q;
        float2 b = *(float2*)(sBh1 + col);
        float v0 = fmaxf(c1[4*f+0] + b.x, 0.0f);
        float v1 = fmaxf(c1[4*f+1] + b.y, 0.0f);
        float v2 = fmaxf(c1[4*f+2] + b.x, 0.0f);
        float v3 = fmaxf(c1[4*f+3] + b.y, 0.0f);

        uint32_t h01 = packhf2(v0, v1);
        uint32_t h23 = packhf2(v2, v3);

        uint32_t abuf = (col >> 6) ? SO_A1 : SO_A0;
        int kc = col & 63;
        uint32_t off = hrow0 + (uint32_t)((((kc >> 3) ^ hrx) << 4) | ((kc & 7) << 1));
        *(uint32_t*)(sm + abuf + off)        = h01;
        *(uint32_t*)(sm + abuf + off + 1024) = h23;
    }
    __syncwarp();

    float c2[64];
    #pragma unroll
    for (int i = 0; i < 64; ++i) c2[i] = 0.0f;

    mb_wait(mb0, ph0); ph0 ^= 1;
    doChunk(SO_A0, SO_B0, c2);
    mb_wait(mb1, ph1); ph1 ^= 1;
    doChunk(SO_A1, SO_B1, c2);

    const int row0 = n0 + r0;
    const int row1 = row0 + 8;
    #pragma unroll
    for (int f = 0; f < 16; ++f) {
        int col = 8 * f + 2 * q;
        float2 b = *(float2*)(sBh2 + col);
        if (row0 < N) {
            float2 v; v.x = c2[4*f+0] + b.x; v.y = c2[4*f+1] + b.y;
            *(float2*)(outH + (size_t)row0 * Fdim + col) = v;
        }
        if (row1 < N) {
            float2 v; v.x = c2[4*f+2] + b.x; v.y = c2[4*f+3] + b.y;
            *(float2*)(outH + (size_t)row1 * Fdim + col) = v;
        }
    }
}

// ---------------- coordinate update -----------------------------------------
__global__ void x_kernel(const float* __restrict__ coord,
                         float* __restrict__ outX,
                         int n3, float C)
{
    int i = blockIdx.x * blockDim.x + threadIdx.x;
    if (i < n3) {
        int n = i / 3, d = i - n * 3;
        outX[i] = coord[i] + g_dx4[(size_t)n * 4 + d] * C;
    }
}

// ---------------- launch -----------------------------------------------------
extern "C" void kernel_launch(void* const* d_in, const int* in_sizes, int n_in,
                              void* d_out, int out_size)
{
    const float* node  = (const float*)d_in[0];
    const float* coord = (const float*)d_in[1];
    const int*   ei    = (const int*)d_in[2];
    const float* We1   = (const float*)d_in[3];
    const float* be1   = (const float*)d_in[4];
    const float* We2   = (const float*)d_in[5];
    const float* be2   = (const float*)d_in[6];
    const float* Wx    = (const float*)d_in[7];
    const float* bx    = (const float*)d_in[8];
    const float* Wh1   = (const float*)d_in[9];
    const float* bh1   = (const float*)d_in[10];
    const float* Wh2   = (const float*)d_in[11];
    const float* bh2   = (const float*)d_in[12];

    const int N = in_sizes[0] / Fdim;
    const int E = in_sizes[2] / 2;

    float* outH = (float*)d_out;
    float* outX = outH + (size_t)N * Fdim;

    cudaFuncSetAttribute(pq_kernel,   cudaFuncAttributeMaxDynamicSharedMemorySize, PQ_SMEM);
    cudaFuncSetAttribute(edge_kernel, cudaFuncAttributeMaxDynamicSharedMemorySize, EDGE_SMEM);
    cudaFuncSetAttribute(node_kernel, cudaFuncAttributeMaxDynamicSharedMemorySize, NODE_SMEM);

    prep_kernel<<<(98304 + 255) / 256, 256>>>(We1, We2, Wh1, Wh2);
    {
        int n_mi = N * 128;
        zero_kernel<<<(n_mi + 255) / 256, 256>>>(node, n_mi, N * 4);
    }
    {
        int grid = (N + ET2 - 1) / ET2;
        pq_kernel<<<grid, 512, PQ_SMEM>>>(be1, N);
    }
    {
        int grid = (E + ET2 - 1) / ET2;
        edge_kernel<<<grid, 512, EDGE_SMEM>>>(coord, ei, We1, be2, Wx, bx, E);
    }
    {
        int grid = (N + ET2 - 1) / ET2;
        node_kernel<<<grid, 512, NODE_SMEM>>>(bh1, bh2, outH, N);
    }
    {
        int n3 = N * 3;
        float C = 1.0f / (float)(N - 1);
        x_kernel<<<(n3 + 255) / 256, 256>>>(coord, outX, n3, C);
    }
}

// round 10
// speedup vs baseline: 1.4148x; 1.4148x over previous
#include <cuda_runtime.h>
#include <cuda_fp16.h>
#include <cstdint>

#define Fdim 128
#define ET2  256              // rows per CTA tile (MMA M)
#define MAXN 50000

// ---------------- scratch (static device arrays; allocation-free) ----------
__device__ float g_mi[(size_t)MAXN * 128];
__device__ float g_dx4[(size_t)MAXN * 4];
__device__ __align__(16) __half g_nodeh[(size_t)MAXN * 128];   // fp16 node table
__device__ __align__(16) __half g_Ph[(size_t)MAXN * 128];      // fp16: node@We1_top + be1
__device__ __align__(16) __half g_Qh[(size_t)MAXN * 128];      // fp16: node@We1_bot
// swizzled fp16 weight chunk images: rows=n(128), kc(64)
__device__ __align__(16) __half gB1[4][8192];   // We1 (k chunks 0..3)
__device__ __align__(16) __half gB2[2][8192];   // We2
__device__ __align__(16) __half gH1[4][8192];   // Wh1
__device__ __align__(16) __half gH2[2][8192];   // Wh2

#define BCH 16384            /* bytes per B chunk */

// ---------------- PTX helpers ----------------------------------------------
__device__ __forceinline__ uint32_t smem_u32(const void* p) {
    uint32_t a;
    asm("{ .reg .u64 t; cvta.to.shared.u64 t, %1; cvt.u32.u64 %0, t; }" : "=r"(a) : "l"(p));
    return a;
}

#define LDSM4(r0, r1, r2, r3, addr) \
    asm volatile("ldmatrix.sync.aligned.m8n8.x4.shared.b16 {%0,%1,%2,%3}, [%4];" \
                 : "=r"(r0), "=r"(r1), "=r"(r2), "=r"(r3) : "r"(addr))

#define MMA16816(cp, a0, a1, a2, a3, b0, b1) \
    asm volatile("mma.sync.aligned.m16n8k16.row.col.f32.f16.f16.f32 " \
                 "{%0,%1,%2,%3},{%4,%5,%6,%7},{%8,%9},{%0,%1,%2,%3};" \
                 : "+f"((cp)[0]), "+f"((cp)[1]), "+f"((cp)[2]), "+f"((cp)[3]) \
                 : "r"(a0), "r"(a1), "r"(a2), "r"(a3), "r"(b0), "r"(b1))

#define MB_INIT(mb, c) asm volatile("mbarrier.init.shared.b64 [%0], %1;" :: "r"(mb), "r"(c) : "memory")
#define MB_EXPECT(mb, b) asm volatile("mbarrier.arrive.expect_tx.shared.b64 _, [%0], %1;" :: "r"(mb), "r"(b) : "memory")
#define BULK_G2S(dst, src, bytes, mb) \
    asm volatile("cp.async.bulk.shared::cluster.global.mbarrier::complete_tx::bytes [%0], [%1], %2, [%3];" \
                 :: "r"(dst), "l"(src), "r"(bytes), "r"(mb) : "memory")

#define CPA16(dst, src, n) \
    asm volatile("cp.async.cg.shared.global [%0], [%1], 16, %2;" :: "r"(dst), "l"(src), "r"(n) : "memory")
#define CPA_COMMIT() asm volatile("cp.async.commit_group;" ::: "memory")
#define CPA_WAIT0()  asm volatile("cp.async.wait_group 0;" ::: "memory")

__device__ __forceinline__ void mb_wait(uint32_t mb, uint32_t parity) {
    uint32_t done;
    asm volatile("{ .reg .pred p; mbarrier.try_wait.parity.acquire.cta.shared::cta.b64 p, [%1], %2; selp.b32 %0, 1, 0, p; }"
                 : "=r"(done) : "r"(mb), "r"(parity) : "memory");
    if (!done) {
        asm volatile("{ .reg .pred P1;\nW%=:\n mbarrier.try_wait.parity.acquire.cta.shared::cta.b64 P1, [%0], %1, 0x989680;\n @P1 bra.uni D%=;\n bra.uni W%=;\nD%=:\n}"
                     :: "r"(mb), "r"(parity) : "memory");
    }
}

__device__ __forceinline__ void red2(float* p, float x, float y) {
    asm volatile("red.global.add.v2.f32 [%0], {%1,%2};" :: "l"(p), "f"(x), "f"(y) : "memory");
}
__device__ __forceinline__ void red4(float* p, float4 v) {
    asm volatile("red.global.add.v4.f32 [%0], {%1,%2,%3,%4};"
                 :: "l"(p), "f"(v.x), "f"(v.y), "f"(v.z), "f"(v.w) : "memory");
}

__device__ __forceinline__ uint32_t packhf2(float a, float b) {
    uint32_t r;
    asm("cvt.rn.f16x2.f32 %0, %1, %2;" : "=r"(r) : "f"(b), "f"(a));
    return r;
}

// packed half2 helpers on raw uint32 bit patterns
__device__ __forceinline__ uint32_t h2_add(uint32_t a, uint32_t b) {
    uint32_t r;
    asm("add.f16x2 %0, %1, %2;" : "=r"(r) : "r"(a), "r"(b));
    return r;
}
__device__ __forceinline__ uint32_t h2_fma(uint32_t a, uint32_t b, uint32_t c) {
    uint32_t r;
    asm("fma.rn.f16x2 %0, %1, %2, %3;" : "=r"(r) : "r"(a), "r"(b), "r"(c));
    return r;
}
__device__ __forceinline__ uint32_t h2_relu(uint32_t a) {
    uint32_t r;
    asm("max.f16x2 %0, %1, %2;" : "=r"(r) : "r"(a), "r"(0u));
    return r;
}

// swizzled element offset within a [row][kc] tile, 64 fp16 per row (128 B)
__host__ __device__ __forceinline__ int swoff(int n, int kc) {
    return n * 64 + ((((kc >> 3) ^ (n & 7)) << 3) | (kc & 7));
}

// ---------------- prep: swizzled fp16 weight chunk images -------------------
__global__ void prep_kernel(const float* __restrict__ We1, const float* __restrict__ We2,
                            const float* __restrict__ Wh1, const float* __restrict__ Wh2)
{
    int id = blockIdx.x * blockDim.x + threadIdx.x;
    if (id < 32768) {
        int c = id >> 13, rem = id & 8191, n = rem >> 6, kc = rem & 63;
        gB1[c][swoff(n, kc)] = __float2half_rn(We1[(size_t)(c * 64 + kc) * 128 + n]);
    } else if (id < 49152) {
        int id2 = id - 32768;
        int c = id2 >> 13, rem = id2 & 8191, n = rem >> 6, kc = rem & 63;
        gB2[c][swoff(n, kc)] = __float2half_rn(We2[(size_t)(c * 64 + kc) * 128 + n]);
    } else if (id < 81920) {
        int id2 = id - 49152;
        int c = id2 >> 13, rem = id2 & 8191, n = rem >> 6, kc = rem & 63;
        gH1[c][swoff(n, kc)] = __float2half_rn(Wh1[(size_t)(c * 64 + kc) * 128 + n]);
    } else if (id < 98304) {
        int id2 = id - 81920;
        int c = id2 >> 13, rem = id2 & 8191, n = rem >> 6, kc = rem & 63;
        gH2[c][swoff(n, kc)] = __float2half_rn(Wh2[(size_t)(c * 64 + kc) * 128 + n]);
    }
}

// ---------------- zero scratch + convert node table to fp16 -----------------
__global__ void zero_kernel(const float* __restrict__ node, int n_mi, int n_dx)
{
    int i = blockIdx.x * blockDim.x + threadIdx.x;
    if (i < n_mi) {
        g_mi[i] = 0.0f;
        g_nodeh[i] = __float2half_rn(node[i]);
    }
    if (i < n_dx) g_dx4[i] = 0.0f;
}

// ---------------- shared SMEM layout -----------------------------------------
#define SO_A0   0
#define SO_A1   32768
#define SO_B0   65536
#define SO_B1   81920
// edge extras
#define SO_DS   98304      /* float4[256] */
#define SO_W    102400     /* float[256] */
#define SO_DST  103424     /* int[256] */
#define SO_WX   104448
#define SO_BE2  104960
#define SO_W256 105472     /* __half[128] = 256 B */
#define SO_MB   105728
#define EDGE_SMEM 105760
// pq extras
#define PQ_BE1  98304
#define PQ_MB   98816
#define PQ_SMEM 98848
// node extras
#define NO_BH1  98304
#define NO_BH2  98816
#define NO_MB   99328
#define NODE_SMEM 99360

// ---------------- PQ precompute: P = node@W_top + be1 ; Q = node@W_bot ------
__global__ __launch_bounds__(512, 1)
void pq_kernel(const float* __restrict__ be1, int N)
{
    extern __shared__ char sm[];
    const uint32_t sbase = smem_u32(sm);
    float* sBe1 = (float*)(sm + PQ_BE1);

    const int t    = threadIdx.x;
    const int wid  = t >> 5;
    const int lane = t & 31;
    const int n0   = blockIdx.x * ET2;

    const uint32_t mb0 = sbase + PQ_MB;
    const uint32_t mb1 = sbase + PQ_MB + 8;

    if (t == 0) { MB_INIT(mb0, 1); MB_INIT(mb1, 1); }
    if (t < 128) sBe1[t] = be1[t];
    __syncthreads();

    if (t == 0) {
        MB_EXPECT(mb0, BCH);
        BULK_G2S(sbase + SO_B0, (const void*)gB1[0], BCH, mb0);
        MB_EXPECT(mb1, BCH);
        BULK_G2S(sbase + SO_B1, (const void*)gB1[1], BCH, mb1);
    }

    const int grow  = t >> 1;
    const int ghalf = t & 1;
    const int grnode = n0 + grow;
    const bool gvalid = grnode < N;
    const int grclamp = gvalid ? grnode : 0;
    const uint32_t g_rowoff = (uint32_t)grow * 128;
    const int      g_rx     = grow & 7;
    const uint32_t g_nsz    = gvalid ? 16u : 0u;

    auto stageN = [&](int c, uint32_t abo) {
        const __half* rp = g_nodeh + (size_t)grclamp * 128 + c * 64 + ghalf * 32;
        #pragma unroll
        for (int u = 0; u < 4; ++u) {
            uint32_t dst = sbase + abo + g_rowoff + (uint32_t)(((ghalf * 4 + u) ^ g_rx) << 4);
            CPA16(dst, rp + u * 8, g_nsz);
        }
        CPA_COMMIT();
    };

    const int seg = lane >> 3;
    const int lnx = lane & 7;
    const int sA_r = seg & 1;
    const int sA_g = (seg >> 1) & 1;
    const int sB_r = (seg >> 1) & 1;
    const int sB_g = seg & 1;
    const uint32_t a_rowoff = (uint32_t)(wid * 16 + lnx + sA_r * 8) * 128;
    const uint32_t b_rowoff = (uint32_t)(lnx + sB_r * 8) * 128;

    auto doChunk = [&](uint32_t Ab, uint32_t Bb, float* cc) {
        #pragma unroll
        for (int ks = 0; ks < 4; ++ks) {
            uint32_t ag = (uint32_t)(((2 * ks) | sA_g) ^ lnx) << 4;
            uint32_t bg = (uint32_t)(((2 * ks) | sB_g) ^ lnx) << 4;
            uint32_t a0,a1,a2,a3;
            LDSM4(a0,a1,a2,a3, sbase + Ab + a_rowoff + ag);
            #pragma unroll
            for (int jb = 0; jb < 8; ++jb) {
                uint32_t baddr = sbase + Bb + b_rowoff + (uint32_t)(jb * 2048) + bg;
                uint32_t b0,b1,b2,b3;
                LDSM4(b0,b1,b2,b3, baddr);
                float* cp0 = cc + 8 * jb;
                float* cp1 = cc + 8 * jb + 4;
                MMA16816(cp0, a0,a1,a2,a3, b0,b1);
                MMA16816(cp1, a0,a1,a2,a3, b2,b3);
            }
        }
    };

    float cc[64];
    #pragma unroll
    for (int i = 0; i < 64; ++i) cc[i] = 0.0f;

    stageN(0, SO_A0);
    stageN(1, SO_A1);
    CPA_WAIT0();
    __syncthreads();

    // P pass: A0@gB1[0] + A1@gB1[1]
    mb_wait(mb0, 0);
    doChunk(SO_A0, SO_B0, cc);
    __syncthreads();
    if (t == 0) { MB_EXPECT(mb0, BCH); BULK_G2S(sbase + SO_B0, (const void*)gB1[2], BCH, mb0); }
    mb_wait(mb1, 0);
    doChunk(SO_A1, SO_B1, cc);
    __syncthreads();
    if (t == 0) { MB_EXPECT(mb1, BCH); BULK_G2S(sbase + SO_B1, (const void*)gB1[3], BCH, mb1); }

    const int r0 = wid * 16 + (lane >> 2);
    const int q  = lane & 3;
    const int row0 = n0 + r0;
    const int row1 = row0 + 8;

    #pragma unroll
    for (int f = 0; f < 16; ++f) {
        int col = 8 * f + 2 * q;
        float2 b = *(float2*)(sBe1 + col);
        if (row0 < N)
            *(uint32_t*)(g_Ph + (size_t)row0 * 128 + col) = packhf2(cc[4*f+0] + b.x, cc[4*f+1] + b.y);
        if (row1 < N)
            *(uint32_t*)(g_Ph + (size_t)row1 * 128 + col) = packhf2(cc[4*f+2] + b.x, cc[4*f+3] + b.y);
    }

    // Q pass: A0@gB1[2] + A1@gB1[3]
    #pragma unroll
    for (int i = 0; i < 64; ++i) cc[i] = 0.0f;
    mb_wait(mb0, 1);
    doChunk(SO_A0, SO_B0, cc);
    mb_wait(mb1, 1);
    doChunk(SO_A1, SO_B1, cc);

    #pragma unroll
    for (int f = 0; f < 16; ++f) {
        int col = 8 * f + 2 * q;
        if (row0 < N)
            *(uint32_t*)(g_Qh + (size_t)row0 * 128 + col) = packhf2(cc[4*f+0], cc[4*f+1]);
        if (row1 < N)
            *(uint32_t*)(g_Qh + (size_t)row1 * 128 + col) = packhf2(cc[4*f+2], cc[4*f+3]);
    }
}

// ---------------- edge kernel: hidden = relu(P[dst]+Q[src]+sq*w256) @ We2 ---
__global__ __launch_bounds__(512, 1)
void edge_kernel(const float* __restrict__ coord,
                 const int*   __restrict__ ei,
                 const float* __restrict__ We1,
                 const float* __restrict__ be2,
                 const float* __restrict__ Wx,
                 const float* __restrict__ bxp,
                 int E)
{
    extern __shared__ char sm[];
    const uint32_t sbase = smem_u32(sm);

    float4* sDS  = (float4*)(sm + SO_DS);
    float*  sW   = (float*)(sm + SO_W);
    int*    sDst = (int*)(sm + SO_DST);
    float*  sWx  = (float*)(sm + SO_WX);
    float*  sBe2 = (float*)(sm + SO_BE2);
    __half* sW256h = (__half*)(sm + SO_W256);

    const int t    = threadIdx.x;
    const int wid  = t >> 5;
    const int lane = t & 31;
    const int e0   = blockIdx.x * ET2;
    const float bx = bxp[0];

    const uint32_t mb0 = sbase + SO_MB;
    const uint32_t mb1 = sbase + SO_MB + 8;

    if (t == 0) { MB_INIT(mb0, 1); MB_INIT(mb1, 1); }

    if (t < ET2) {
        int eg = e0 + t;
        float dx = 0.f, dy = 0.f, dz = 0.f;
        int di = -1;
        if (eg < E) {
            int si = ei[eg];
            di     = ei[E + eg];
            dx = coord[(size_t)di * 3 + 0] - coord[(size_t)si * 3 + 0];
            dy = coord[(size_t)di * 3 + 1] - coord[(size_t)si * 3 + 1];
            dz = coord[(size_t)di * 3 + 2] - coord[(size_t)si * 3 + 2];
        }
        sDS[t]  = make_float4(dx, dy, dz, dx * dx + dy * dy + dz * dz);
        sDst[t] = di;
    }
    if (t < 128) {
        sWx[t]  = Wx[t];
        sBe2[t] = be2[t];
        sW256h[t] = __float2half_rn(We1[(size_t)256 * 128 + t]);
    }
    __syncthreads();

    if (t == 0) {
        MB_EXPECT(mb0, BCH);
        BULK_G2S(sbase + SO_B0, (const void*)gB2[0], BCH, mb0);
        MB_EXPECT(mb1, BCH);
        BULK_G2S(sbase + SO_B1, (const void*)gB2[1], BCH, mb1);
    }

    // gather role: 2 threads per edge row
    const int grow  = t >> 1;
    const int ghalf = t & 1;
    int gsi = 0, gdi = 0;
    const bool gvalid = (e0 + grow) < E;
    if (gvalid) { gsi = ei[e0 + grow]; gdi = ei[E + e0 + grow]; }
    const uint32_t g_rowoff = (uint32_t)grow * 128;
    const int      g_rx     = grow & 7;

    // stage hidden chunk c: relu(P[dst]+Q[src]+sq*w256) in packed half2
    const uint32_t sq2 = packhf2(sDS[grow].w, sDS[grow].w);
    auto stageH = [&](int c, uint32_t abo) {
        const int cb = c * 64 + ghalf * 32;
        const uint4* pp = (const uint4*)(g_Ph + (size_t)gdi * 128 + cb);
        const uint4* qq = (const uint4*)(g_Qh + (size_t)gsi * 128 + cb);
        const uint4* ww = (const uint4*)(sW256h + cb);
        #pragma unroll
        for (int u = 0; u < 4; ++u) {
            uint4 P = pp[u];
            uint4 Q = qq[u];
            uint4 W = ww[u];
            uint4 H;
            H.x = h2_relu(h2_fma(sq2, W.x, h2_add(P.x, Q.x)));
            H.y = h2_relu(h2_fma(sq2, W.y, h2_add(P.y, Q.y)));
            H.z = h2_relu(h2_fma(sq2, W.z, h2_add(P.z, Q.z)));
            H.w = h2_relu(h2_fma(sq2, W.w, h2_add(P.w, Q.w)));
            uint32_t off = g_rowoff + (uint32_t)(((ghalf * 4 + u) ^ g_rx) << 4);
            *(uint4*)(sm + abo + off) = H;
        }
    };

    const int seg = lane >> 3;
    const int lnx = lane & 7;
    const int sA_r = seg & 1;
    const int sA_g = (seg >> 1) & 1;
    const int sB_r = (seg >> 1) & 1;
    const int sB_g = seg & 1;
    const uint32_t a_rowoff = (uint32_t)(wid * 16 + lnx + sA_r * 8) * 128;
    const uint32_t b_rowoff = (uint32_t)(lnx + sB_r * 8) * 128;

    auto doChunk = [&](uint32_t Ab, uint32_t Bb, float* cc) {
        #pragma unroll
        for (int ks = 0; ks < 4; ++ks) {
            uint32_t ag = (uint32_t)(((2 * ks) | sA_g) ^ lnx) << 4;
            uint32_t bg = (uint32_t)(((2 * ks) | sB_g) ^ lnx) << 4;
            uint32_t a0,a1,a2,a3;
            LDSM4(a0,a1,a2,a3, sbase + Ab + a_rowoff + ag);
            #pragma unroll
            for (int jb = 0; jb < 8; ++jb) {
                uint32_t baddr = sbase + Bb + b_rowoff + (uint32_t)(jb * 2048) + bg;
                uint32_t b0,b1,b2,b3;
                LDSM4(b0,b1,b2,b3, baddr);
                float* cp0 = cc + 8 * jb;
                float* cp1 = cc + 8 * jb + 4;
                MMA16816(cp0, a0,a1,a2,a3, b0,b1);
                MMA16816(cp1, a0,a1,a2,a3, b2,b3);
            }
        }
    };

    float c2[64];
    #pragma unroll
    for (int i = 0; i < 64; ++i) c2[i] = 0.0f;

    stageH(0, SO_A0);
    __syncthreads();
    stageH(1, SO_A1);          // LDGs overlap chunk-0 MMAs below

    mb_wait(mb0, 0);
    doChunk(SO_A0, SO_B0, c2);
    __syncthreads();           // A1 fully staged

    mb_wait(mb1, 0);
    doChunk(SO_A1, SO_B1, c2);

    // ============ epilogue: bias, scalar head, register-direct scatter ======
    const int r0 = wid * 16 + (lane >> 2);
    const int q  = lane & 3;
    const int dst0 = sDst[r0];
    const int dst1 = sDst[r0 + 8];
    float w0 = 0.0f, w1 = 0.0f;
    #pragma unroll
    for (int f = 0; f < 16; ++f) {
        int col = 8 * f + 2 * q;
        float2 b  = *(float2*)(sBe2 + col);
        float2 wx = *(float2*)(sWx + col);
        float v0 = c2[4*f+0] + b.x;
        float v1 = c2[4*f+1] + b.y;
        float v2 = c2[4*f+2] + b.x;
        float v3 = c2[4*f+3] + b.y;
        w0 = fmaf(v0, wx.x, fmaf(v1, wx.y, w0));
        w1 = fmaf(v2, wx.x, fmaf(v3, wx.y, w1));
        if (dst0 >= 0) red2(g_mi + (size_t)dst0 * 128 + col, v0, v1);
        if (dst1 >= 0) red2(g_mi + (size_t)dst1 * 128 + col, v2, v3);
    }
    w0 += __shfl_xor_sync(0xffffffffu, w0, 1);
    w0 += __shfl_xor_sync(0xffffffffu, w0, 2);
    w1 += __shfl_xor_sync(0xffffffffu, w1, 1);
    w1 += __shfl_xor_sync(0xffffffffu, w1, 2);
    if (q == 0) {
        sW[r0]     = w0 + bx;
        sW[r0 + 8] = w1 + bx;
    }
    __syncthreads();

    if (t < ET2) {
        int di = sDst[t];
        if (di >= 0) {
            float w = sW[t];
            float4 ds = sDS[t];
            red4(g_dx4 + (size_t)di * 4, make_float4(ds.x * w, ds.y * w, ds.z * w, 0.0f));
        }
    }
}

// ---------------- node kernel: fp16 MMA [node|m_i] @ Wh1 -> relu -> @ Wh2 ---
__global__ __launch_bounds__(512, 1)
void node_kernel(const float* __restrict__ bh1,
                 const float* __restrict__ bh2,
                 float* __restrict__ outH,
                 int N)
{
    extern __shared__ char sm[];
    const uint32_t sbase = smem_u32(sm);

    float* sBh1 = (float*)(sm + NO_BH1);
    float* sBh2 = (float*)(sm + NO_BH2);

    const int t    = threadIdx.x;
    const int wid  = t >> 5;
    const int lane = t & 31;
    const int n0   = blockIdx.x * ET2;

    const uint32_t mb0 = sbase + NO_MB;
    const uint32_t mb1 = sbase + NO_MB + 8;

    if (t == 0) { MB_INIT(mb0, 1); MB_INIT(mb1, 1); }
    if (t < 128) {
        sBh1[t] = bh1[t];
        sBh2[t] = bh2[t];
    }
    __syncthreads();

    if (t == 0) {
        MB_EXPECT(mb0, BCH);
        BULK_G2S(sbase + SO_B0, (const void*)gH1[0], BCH, mb0);
        MB_EXPECT(mb1, BCH);
        BULK_G2S(sbase + SO_B1, (const void*)gH1[1], BCH, mb1);
    }

    const int grow  = t >> 1;
    const int ghalf = t & 1;
    const int grnode = n0 + grow;
    const bool gvalid = grnode < N;
    const int grclamp = gvalid ? grnode : 0;
    const uint32_t g_rowoff = (uint32_t)grow * 128;
    const int      g_rx     = grow & 7;
    const uint32_t g_nsz    = gvalid ? 16u : 0u;

    auto stageN = [&](int c, uint32_t abo) {
        const __half* rp = g_nodeh + (size_t)grclamp * 128 + c * 64 + ghalf * 32;
        #pragma unroll
        for (int u = 0; u < 4; ++u) {
            uint32_t dst = sbase + abo + g_rowoff + (uint32_t)(((ghalf * 4 + u) ^ g_rx) << 4);
            CPA16(dst, rp + u * 8, g_nsz);
        }
        CPA_COMMIT();
    };
    auto stageM = [&](int c, uint32_t abo) {
        const float* rp = g_mi + (size_t)grclamp * 128 + (c - 2) * 64 + ghalf * 32;
        #pragma unroll
        for (int u = 0; u < 4; ++u) {
            uint4 H;
            if (gvalid) {
                float4 v0 = *(const float4*)(rp + u * 8);
                float4 v1 = *(const float4*)(rp + u * 8 + 4);
                H.x = packhf2(v0.x, v0.y);
                H.y = packhf2(v0.z, v0.w);
                H.z = packhf2(v1.x, v1.y);
                H.w = packhf2(v1.z, v1.w);
            } else {
                H = make_uint4(0u, 0u, 0u, 0u);
            }
            uint32_t off = g_rowoff + (uint32_t)(((ghalf * 4 + u) ^ g_rx) << 4);
            *(uint4*)(sm + abo + off) = H;
        }
    };

    const int seg = lane >> 3;
    const int lnx = lane & 7;
    const int sA_r = seg & 1;
    const int sA_g = (seg >> 1) & 1;
    const int sB_r = (seg >> 1) & 1;
    const int sB_g = seg & 1;
    const uint32_t a_rowoff = (uint32_t)(wid * 16 + lnx + sA_r * 8) * 128;
    const uint32_t b_rowoff = (uint32_t)(lnx + sB_r * 8) * 128;

    auto doChunk = [&](uint32_t Ab, uint32_t Bb, float* cc) {
        #pragma unroll
        for (int ks = 0; ks < 4; ++ks) {
            uint32_t ag = (uint32_t)(((2 * ks) | sA_g) ^ lnx) << 4;
            uint32_t bg = (uint32_t)(((2 * ks) | sB_g) ^ lnx) << 4;
            uint32_t a0,a1,a2,a3;
            LDSM4(a0,a1,a2,a3, sbase + Ab + a_rowoff + ag);
            #pragma unroll
            for (int jb = 0; jb < 8; ++jb) {
                uint32_t baddr = sbase + Bb + b_rowoff + (uint32_t)(jb * 2048) + bg;
                uint32_t b0,b1,b2,b3;
                LDSM4(b0,b1,b2,b3, baddr);
                float* cp0 = cc + 8 * jb;
                float* cp1 = cc + 8 * jb + 4;
                MMA16816(cp0, a0,a1,a2,a3, b0,b1);
                MMA16816(cp1, a0,a1,a2,a3, b2,b3);
            }
        }
    };

    float c1[64];
    #pragma unroll
    for (int i = 0; i < 64; ++i) c1[i] = 0.0f;

    stageN(0, SO_A0);
    CPA_WAIT0();
    __syncthreads();

    uint32_t ph0 = 0, ph1 = 0;

    #pragma unroll 1
    for (int c = 0; c < 4; ++c) {
        if (c & 1) { mb_wait(mb1, ph1); ph1 ^= 1; }
        else       { mb_wait(mb0, ph0); ph0 ^= 1; }

        if (c == 0)      stageN(1, SO_A1);
        else if (c == 1) stageM(2, SO_A0);
        else if (c == 2) stageM(3, SO_A1);

        doChunk((c & 1) ? SO_A1 : SO_A0, (c & 1) ? SO_B1 : SO_B0, c1);
        CPA_WAIT0();
        __syncthreads();

        if (t == 0) {
            const void* nsrc = (c == 0) ? (const void*)gH1[2]
                             : (c == 1) ? (const void*)gH1[3]
                             : (c == 2) ? (const void*)gH2[0]
                                        : (const void*)gH2[1];
            uint32_t dst = (c & 1) ? (sbase + SO_B1) : (sbase + SO_B0);
            uint32_t mb  = (c & 1) ? mb1 : mb0;
            MB_EXPECT(mb, BCH);
            BULK_G2S(dst, nsrc, BCH, mb);
        }
    }

    const int r0 = wid * 16 + (lane >> 2);
    const int q  = lane & 3;
    const uint32_t hrow0 = (uint32_t)r0 * 128;
    const int      hrx   = r0 & 7;
    #pragma unroll
    for (int f = 0; f < 16; ++f) {
        int col = 8 * f + 2 * q;
        float2 b = *(float2*)(sBh1 + col);
        float v0 = fmaxf(c1[4*f+0] + b.x, 0.0f);
        float v1 = fmaxf(c1[4*f+1] + b.y, 0.0f);
        float v2 = fmaxf(c1[4*f+2] + b.x, 0.0f);
        float v3 = fmaxf(c1[4*f+3] + b.y, 0.0f);

        uint32_t h01 = packhf2(v0, v1);
        uint32_t h23 = packhf2(v2, v3);

        uint32_t abuf = (col >> 6) ? SO_A1 : SO_A0;
        int kc = col & 63;
        uint32_t off = hrow0 + (uint32_t)((((kc >> 3) ^ hrx) << 4) | ((kc & 7) << 1));
        *(uint32_t*)(sm + abuf + off)        = h01;
        *(uint32_t*)(sm + abuf + off + 1024) = h23;
    }
    __syncwarp();

    float c2[64];
    #pragma unroll
    for (int i = 0; i < 64; ++i) c2[i] = 0.0f;

    mb_wait(mb0, ph0); ph0 ^= 1;
    doChunk(SO_A0, SO_B0, c2);
    mb_wait(mb1, ph1); ph1 ^= 1;
    doChunk(SO_A1, SO_B1, c2);

    const int row0 = n0 + r0;
    const int row1 = row0 + 8;
    #pragma unroll
    for (int f = 0; f < 16; ++f) {
        int col = 8 * f + 2 * q;
        float2 b = *(float2*)(sBh2 + col);
        if (row0 < N) {
            float2 v; v.x = c2[4*f+0] + b.x; v.y = c2[4*f+1] + b.y;
            *(float2*)(outH + (size_t)row0 * Fdim + col) = v;
        }
        if (row1 < N) {
            float2 v; v.x = c2[4*f+2] + b.x; v.y = c2[4*f+3] + b.y;
            *(float2*)(outH + (size_t)row1 * Fdim + col) = v;
        }
    }
}

// ---------------- coordinate update -----------------------------------------
__global__ void x_kernel(const float* __restrict__ coord,
                         float* __restrict__ outX,
                         int n3, float C)
{
    int i = blockIdx.x * blockDim.x + threadIdx.x;
    if (i < n3) {
        int n = i / 3, d = i - n * 3;
        outX[i] = coord[i] + g_dx4[(size_t)n * 4 + d] * C;
    }
}

// ---------------- launch -----------------------------------------------------
extern "C" void kernel_launch(void* const* d_in, const int* in_sizes, int n_in,
                              void* d_out, int out_size)
{
    const float* node  = (const float*)d_in[0];
    const float* coord = (const float*)d_in[1];
    const int*   ei    = (const int*)d_in[2];
    const float* We1   = (const float*)d_in[3];
    const float* be1   = (const float*)d_in[4];
    const float* We2   = (const float*)d_in[5];
    const float* be2   = (const float*)d_in[6];
    const float* Wx    = (const float*)d_in[7];
    const float* bx    = (const float*)d_in[8];
    const float* Wh1   = (const float*)d_in[9];
    const float* bh1   = (const float*)d_in[10];
    const float* Wh2   = (const float*)d_in[11];
    const float* bh2   = (const float*)d_in[12];

    const int N = in_sizes[0] / Fdim;
    const int E = in_sizes[2] / 2;

    float* outH = (float*)d_out;
    float* outX = outH + (size_t)N * Fdim;

    cudaFuncSetAttribute(pq_kernel,   cudaFuncAttributeMaxDynamicSharedMemorySize, PQ_SMEM);
    cudaFuncSetAttribute(edge_kernel, cudaFuncAttributeMaxDynamicSharedMemorySize, EDGE_SMEM);
    cudaFuncSetAttribute(node_kernel, cudaFuncAttributeMaxDynamicSharedMemorySize, NODE_SMEM);

    prep_kernel<<<(98304 + 255) / 256, 256>>>(We1, We2, Wh1, Wh2);
    {
        int n_mi = N * 128;
        zero_kernel<<<(n_mi + 255) / 256, 256>>>(node, n_mi, N * 4);
    }
    {
        int grid = (N + ET2 - 1) / ET2;
        pq_kernel<<<grid, 512, PQ_SMEM>>>(be1, N);
    }
    {
        int grid = (E + ET2 - 1) / ET2;
        edge_kernel<<<grid, 512, EDGE_SMEM>>>(coord, ei, We1, be2, Wx, bx, E);
    }
    {
        int grid = (N + ET2 - 1) / ET2;
        node_kernel<<<grid, 512, NODE_SMEM>>>(bh1, bh2, outH, N);
    }
    {
        int n3 = N * 3;
        float C = 1.0f / (float)(N - 1);
        x_kernel<<<(n3 + 255) / 256, 256>>>(coord, outX, n3, C);
    }
}

// round 11
// speedup vs baseline: 1.5506x; 1.0960x over previous
#include <cuda_runtime.h>
#include <cuda_fp16.h>
#include <cstdint>

#define Fdim 128
#define ET2  256              // rows per CTA tile for pq/node kernels
#define ETE  128              // edges per CTA tile (edge kernel)
#define MAXN 50000

// ---------------- scratch (static device arrays; allocation-free) ----------
__device__ float g_mi[(size_t)MAXN * 128];
__device__ float g_dx4[(size_t)MAXN * 4];
__device__ __align__(16) __half g_nodeh[(size_t)MAXN * 128];   // fp16 node table
__device__ __align__(16) __half g_Ph[(size_t)MAXN * 128];      // fp16: node@We1_top + be1
__device__ __align__(16) __half g_Qh[(size_t)MAXN * 128];      // fp16: node@We1_bot
// swizzled fp16 weight chunk images: rows=n(128), kc(64)
__device__ __align__(16) __half gB1[4][8192];   // We1 (k chunks 0..3)
__device__ __align__(16) __half gB2[2][8192];   // We2
__device__ __align__(16) __half gH1[4][8192];   // Wh1
__device__ __align__(16) __half gH2[2][8192];   // Wh2

#define BCH 16384            /* bytes per B chunk */

// ---------------- PTX helpers ----------------------------------------------
__device__ __forceinline__ uint32_t smem_u32(const void* p) {
    uint32_t a;
    asm("{ .reg .u64 t; cvta.to.shared.u64 t, %1; cvt.u32.u64 %0, t; }" : "=r"(a) : "l"(p));
    return a;
}

#define LDSM4(r0, r1, r2, r3, addr) \
    asm volatile("ldmatrix.sync.aligned.m8n8.x4.shared.b16 {%0,%1,%2,%3}, [%4];" \
                 : "=r"(r0), "=r"(r1), "=r"(r2), "=r"(r3) : "r"(addr))

#define MMA16816(cp, a0, a1, a2, a3, b0, b1) \
    asm volatile("mma.sync.aligned.m16n8k16.row.col.f32.f16.f16.f32 " \
                 "{%0,%1,%2,%3},{%4,%5,%6,%7},{%8,%9},{%0,%1,%2,%3};" \
                 : "+f"((cp)[0]), "+f"((cp)[1]), "+f"((cp)[2]), "+f"((cp)[3]) \
                 : "r"(a0), "r"(a1), "r"(a2), "r"(a3), "r"(b0), "r"(b1))

#define MB_INIT(mb, c) asm volatile("mbarrier.init.shared.b64 [%0], %1;" :: "r"(mb), "r"(c) : "memory")
#define MB_EXPECT(mb, b) asm volatile("mbarrier.arrive.expect_tx.shared.b64 _, [%0], %1;" :: "r"(mb), "r"(b) : "memory")
#define BULK_G2S(dst, src, bytes, mb) \
    asm volatile("cp.async.bulk.shared::cluster.global.mbarrier::complete_tx::bytes [%0], [%1], %2, [%3];" \
                 :: "r"(dst), "l"(src), "r"(bytes), "r"(mb) : "memory")

#define CPA16(dst, src, n) \
    asm volatile("cp.async.cg.shared.global [%0], [%1], 16, %2;" :: "r"(dst), "l"(src), "r"(n) : "memory")
#define CPA_COMMIT() asm volatile("cp.async.commit_group;" ::: "memory")
#define CPA_WAIT0()  asm volatile("cp.async.wait_group 0;" ::: "memory")

__device__ __forceinline__ void mb_wait(uint32_t mb, uint32_t parity) {
    uint32_t done;
    asm volatile("{ .reg .pred p; mbarrier.try_wait.parity.acquire.cta.shared::cta.b64 p, [%1], %2; selp.b32 %0, 1, 0, p; }"
                 : "=r"(done) : "r"(mb), "r"(parity) : "memory");
    if (!done) {
        asm volatile("{ .reg .pred P1;\nW%=:\n mbarrier.try_wait.parity.acquire.cta.shared::cta.b64 P1, [%0], %1, 0x989680;\n @P1 bra.uni D%=;\n bra.uni W%=;\nD%=:\n}"
                     :: "r"(mb), "r"(parity) : "memory");
    }
}

__device__ __forceinline__ void red2(float* p, float x, float y) {
    asm volatile("red.global.add.v2.f32 [%0], {%1,%2};" :: "l"(p), "f"(x), "f"(y) : "memory");
}
__device__ __forceinline__ void red4(float* p, float4 v) {
    asm volatile("red.global.add.v4.f32 [%0], {%1,%2,%3,%4};"
                 :: "l"(p), "f"(v.x), "f"(v.y), "f"(v.z), "f"(v.w) : "memory");
}

__device__ __forceinline__ uint32_t packhf2(float a, float b) {
    uint32_t r;
    asm("cvt.rn.f16x2.f32 %0, %1, %2;" : "=r"(r) : "f"(b), "f"(a));
    return r;
}

// packed half2 helpers on raw uint32 bit patterns
__device__ __forceinline__ uint32_t h2_add(uint32_t a, uint32_t b) {
    uint32_t r;
    asm("add.f16x2 %0, %1, %2;" : "=r"(r) : "r"(a), "r"(b));
    return r;
}
__device__ __forceinline__ uint32_t h2_fma(uint32_t a, uint32_t b, uint32_t c) {
    uint32_t r;
    asm("fma.rn.f16x2 %0, %1, %2, %3;" : "=r"(r) : "r"(a), "r"(b), "r"(c));
    return r;
}
__device__ __forceinline__ uint32_t h2_relu(uint32_t a) {
    uint32_t r;
    asm("max.f16x2 %0, %1, %2;" : "=r"(r) : "r"(a), "r"(0u));
    return r;
}

// swizzled element offset within a [row][kc] tile, 64 fp16 per row (128 B)
__host__ __device__ __forceinline__ int swoff(int n, int kc) {
    return n * 64 + ((((kc >> 3) ^ (n & 7)) << 3) | (kc & 7));
}

// ---------------- prep: swizzled fp16 weight chunk images -------------------
__global__ void prep_kernel(const float* __restrict__ We1, const float* __restrict__ We2,
                            const float* __restrict__ Wh1, const float* __restrict__ Wh2)
{
    int id = blockIdx.x * blockDim.x + threadIdx.x;
    if (id < 32768) {
        int c = id >> 13, rem = id & 8191, n = rem >> 6, kc = rem & 63;
        gB1[c][swoff(n, kc)] = __float2half_rn(We1[(size_t)(c * 64 + kc) * 128 + n]);
    } else if (id < 49152) {
        int id2 = id - 32768;
        int c = id2 >> 13, rem = id2 & 8191, n = rem >> 6, kc = rem & 63;
        gB2[c][swoff(n, kc)] = __float2half_rn(We2[(size_t)(c * 64 + kc) * 128 + n]);
    } else if (id < 81920) {
        int id2 = id - 49152;
        int c = id2 >> 13, rem = id2 & 8191, n = rem >> 6, kc = rem & 63;
        gH1[c][swoff(n, kc)] = __float2half_rn(Wh1[(size_t)(c * 64 + kc) * 128 + n]);
    } else if (id < 98304) {
        int id2 = id - 81920;
        int c = id2 >> 13, rem = id2 & 8191, n = rem >> 6, kc = rem & 63;
        gH2[c][swoff(n, kc)] = __float2half_rn(Wh2[(size_t)(c * 64 + kc) * 128 + n]);
    }
}

// ---------------- zero scratch + convert node table to fp16 -----------------
__global__ void zero_kernel(const float* __restrict__ node, int n_mi, int n_dx)
{
    int i = blockIdx.x * blockDim.x + threadIdx.x;
    if (i < n_mi) {
        g_mi[i] = 0.0f;
        g_nodeh[i] = __float2half_rn(node[i]);
    }
    if (i < n_dx) g_dx4[i] = 0.0f;
}

// ---------------- SMEM layouts ------------------------------------------------
// pq / node kernels (512 threads, 256-row tiles)
#define SO_A0   0
#define SO_A1   32768
#define SO_B0   65536
#define SO_B1   81920
#define PQ_BE1  98304
#define PQ_MB   98816
#define PQ_SMEM 98848
#define NO_BH1  98304
#define NO_BH2  98816
#define NO_MB   99328
#define NODE_SMEM 99360
// edge kernel (256 threads, 128-edge tiles, 2 CTAs/SM)
#define EO_A0   0
#define EO_A1   16384
#define EO_B0   32768
#define EO_B1   49152
#define EO_DS   65536      /* float4[128] */
#define EO_W    67584      /* float[128] */
#define EO_DST  68096      /* int[128] */
#define EO_WX   68608
#define EO_BE2  69120
#define EO_W256 69632      /* __half[128] */
#define EO_MB   69888
#define EDGE_SMEM 69920

// ---------------- PQ precompute: P = node@W_top + be1 ; Q = node@W_bot ------
__global__ __launch_bounds__(512, 1)
void pq_kernel(const float* __restrict__ be1, int N)
{
    extern __shared__ char sm[];
    const uint32_t sbase = smem_u32(sm);
    float* sBe1 = (float*)(sm + PQ_BE1);

    const int t    = threadIdx.x;
    const int wid  = t >> 5;
    const int lane = t & 31;
    const int n0   = blockIdx.x * ET2;

    const uint32_t mb0 = sbase + PQ_MB;
    const uint32_t mb1 = sbase + PQ_MB + 8;

    if (t == 0) { MB_INIT(mb0, 1); MB_INIT(mb1, 1); }
    if (t < 128) sBe1[t] = be1[t];
    __syncthreads();

    if (t == 0) {
        MB_EXPECT(mb0, BCH);
        BULK_G2S(sbase + SO_B0, (const void*)gB1[0], BCH, mb0);
        MB_EXPECT(mb1, BCH);
        BULK_G2S(sbase + SO_B1, (const void*)gB1[1], BCH, mb1);
    }

    const int grow  = t >> 1;
    const int ghalf = t & 1;
    const int grnode = n0 + grow;
    const bool gvalid = grnode < N;
    const int grclamp = gvalid ? grnode : 0;
    const uint32_t g_rowoff = (uint32_t)grow * 128;
    const int      g_rx     = grow & 7;
    const uint32_t g_nsz    = gvalid ? 16u : 0u;

    auto stageN = [&](int c, uint32_t abo) {
        const __half* rp = g_nodeh + (size_t)grclamp * 128 + c * 64 + ghalf * 32;
        #pragma unroll
        for (int u = 0; u < 4; ++u) {
            uint32_t dst = sbase + abo + g_rowoff + (uint32_t)(((ghalf * 4 + u) ^ g_rx) << 4);
            CPA16(dst, rp + u * 8, g_nsz);
        }
        CPA_COMMIT();
    };

    const int seg = lane >> 3;
    const int lnx = lane & 7;
    const int sA_r = seg & 1;
    const int sA_g = (seg >> 1) & 1;
    const int sB_r = (seg >> 1) & 1;
    const int sB_g = seg & 1;
    const uint32_t a_rowoff = (uint32_t)(wid * 16 + lnx + sA_r * 8) * 128;
    const uint32_t b_rowoff = (uint32_t)(lnx + sB_r * 8) * 128;

    auto doChunk = [&](uint32_t Ab, uint32_t Bb, float* cc) {
        #pragma unroll
        for (int ks = 0; ks < 4; ++ks) {
            uint32_t ag = (uint32_t)(((2 * ks) | sA_g) ^ lnx) << 4;
            uint32_t bg = (uint32_t)(((2 * ks) | sB_g) ^ lnx) << 4;
            uint32_t a0,a1,a2,a3;
            LDSM4(a0,a1,a2,a3, sbase + Ab + a_rowoff + ag);
            #pragma unroll
            for (int jb = 0; jb < 8; ++jb) {
                uint32_t baddr = sbase + Bb + b_rowoff + (uint32_t)(jb * 2048) + bg;
                uint32_t b0,b1,b2,b3;
                LDSM4(b0,b1,b2,b3, baddr);
                float* cp0 = cc + 8 * jb;
                float* cp1 = cc + 8 * jb + 4;
                MMA16816(cp0, a0,a1,a2,a3, b0,b1);
                MMA16816(cp1, a0,a1,a2,a3, b2,b3);
            }
        }
    };

    float cc[64];
    #pragma unroll
    for (int i = 0; i < 64; ++i) cc[i] = 0.0f;

    stageN(0, SO_A0);
    stageN(1, SO_A1);
    CPA_WAIT0();
    __syncthreads();

    // P pass: A0@gB1[0] + A1@gB1[1]
    mb_wait(mb0, 0);
    doChunk(SO_A0, SO_B0, cc);
    __syncthreads();
    if (t == 0) { MB_EXPECT(mb0, BCH); BULK_G2S(sbase + SO_B0, (const void*)gB1[2], BCH, mb0); }
    mb_wait(mb1, 0);
    doChunk(SO_A1, SO_B1, cc);
    __syncthreads();
    if (t == 0) { MB_EXPECT(mb1, BCH); BULK_G2S(sbase + SO_B1, (const void*)gB1[3], BCH, mb1); }

    const int r0 = wid * 16 + (lane >> 2);
    const int q  = lane & 3;
    const int row0 = n0 + r0;
    const int row1 = row0 + 8;

    #pragma unroll
    for (int f = 0; f < 16; ++f) {
        int col = 8 * f + 2 * q;
        float2 b = *(float2*)(sBe1 + col);
        if (row0 < N)
            *(uint32_t*)(g_Ph + (size_t)row0 * 128 + col) = packhf2(cc[4*f+0] + b.x, cc[4*f+1] + b.y);
        if (row1 < N)
            *(uint32_t*)(g_Ph + (size_t)row1 * 128 + col) = packhf2(cc[4*f+2] + b.x, cc[4*f+3] + b.y);
    }

    // Q pass: A0@gB1[2] + A1@gB1[3]
    #pragma unroll
    for (int i = 0; i < 64; ++i) cc[i] = 0.0f;
    mb_wait(mb0, 1);
    doChunk(SO_A0, SO_B0, cc);
    mb_wait(mb1, 1);
    doChunk(SO_A1, SO_B1, cc);

    #pragma unroll
    for (int f = 0; f < 16; ++f) {
        int col = 8 * f + 2 * q;
        if (row0 < N)
            *(uint32_t*)(g_Qh + (size_t)row0 * 128 + col) = packhf2(cc[4*f+0], cc[4*f+1]);
        if (row1 < N)
            *(uint32_t*)(g_Qh + (size_t)row1 * 128 + col) = packhf2(cc[4*f+2], cc[4*f+3]);
    }
}

// ---------------- edge kernel: hidden = relu(P[dst]+Q[src]+sq*w256) @ We2 ---
// 256 threads, 128-edge tile, 2 CTAs/SM
__global__ __launch_bounds__(256, 2)
void edge_kernel(const float* __restrict__ coord,
                 const int*   __restrict__ ei,
                 const float* __restrict__ We1,
                 const float* __restrict__ be2,
                 const float* __restrict__ Wx,
                 const float* __restrict__ bxp,
                 int E)
{
    extern __shared__ char sm[];
    const uint32_t sbase = smem_u32(sm);

    float4* sDS  = (float4*)(sm + EO_DS);
    float*  sW   = (float*)(sm + EO_W);
    int*    sDst = (int*)(sm + EO_DST);
    float*  sWx  = (float*)(sm + EO_WX);
    float*  sBe2 = (float*)(sm + EO_BE2);
    __half* sW256h = (__half*)(sm + EO_W256);

    const int t    = threadIdx.x;
    const int wid  = t >> 5;
    const int lane = t & 31;
    const int e0   = blockIdx.x * ETE;
    const float bx = bxp[0];

    const uint32_t mb0 = sbase + EO_MB;
    const uint32_t mb1 = sbase + EO_MB + 8;

    if (t == 0) { MB_INIT(mb0, 1); MB_INIT(mb1, 1); }

    if (t < ETE) {
        int eg = e0 + t;
        float dx = 0.f, dy = 0.f, dz = 0.f;
        int di = -1;
        if (eg < E) {
            int si = ei[eg];
            di     = ei[E + eg];
            dx = coord[(size_t)di * 3 + 0] - coord[(size_t)si * 3 + 0];
            dy = coord[(size_t)di * 3 + 1] - coord[(size_t)si * 3 + 1];
            dz = coord[(size_t)di * 3 + 2] - coord[(size_t)si * 3 + 2];
        }
        sDS[t]  = make_float4(dx, dy, dz, dx * dx + dy * dy + dz * dz);
        sDst[t] = di;
    }
    if (t < 128) {
        sWx[t]  = Wx[t];
        sBe2[t] = be2[t];
        sW256h[t] = __float2half_rn(We1[(size_t)256 * 128 + t]);
    }
    __syncthreads();

    if (t == 0) {
        MB_EXPECT(mb0, BCH);
        BULK_G2S(sbase + EO_B0, (const void*)gB2[0], BCH, mb0);
        MB_EXPECT(mb1, BCH);
        BULK_G2S(sbase + EO_B1, (const void*)gB2[1], BCH, mb1);
    }

    // gather role: 2 threads per edge row
    const int grow  = t >> 1;          // 0..127
    const int ghalf = t & 1;
    int gsi = 0, gdi = 0;
    const bool gvalid = (e0 + grow) < E;
    if (gvalid) { gsi = ei[e0 + grow]; gdi = ei[E + e0 + grow]; }
    const uint32_t g_rowoff = (uint32_t)grow * 128;
    const int      g_rx     = grow & 7;

    const uint32_t sq2 = packhf2(sDS[grow].w, sDS[grow].w);
    auto stageH = [&](int c, uint32_t abo) {
        const int cb = c * 64 + ghalf * 32;
        const uint4* pp = (const uint4*)(g_Ph + (size_t)gdi * 128 + cb);
        const uint4* qq = (const uint4*)(g_Qh + (size_t)gsi * 128 + cb);
        const uint4* ww = (const uint4*)(sW256h + cb);
        #pragma unroll
        for (int u = 0; u < 4; ++u) {
            uint4 P = pp[u];
            uint4 Q = qq[u];
            uint4 W = ww[u];
            uint4 H;
            H.x = h2_relu(h2_fma(sq2, W.x, h2_add(P.x, Q.x)));
            H.y = h2_relu(h2_fma(sq2, W.y, h2_add(P.y, Q.y)));
            H.z = h2_relu(h2_fma(sq2, W.z, h2_add(P.z, Q.z)));
            H.w = h2_relu(h2_fma(sq2, W.w, h2_add(P.w, Q.w)));
            uint32_t off = g_rowoff + (uint32_t)(((ghalf * 4 + u) ^ g_rx) << 4);
            *(uint4*)(sm + abo + off) = H;
        }
    };

    const int seg = lane >> 3;
    const int lnx = lane & 7;
    const int sA_r = seg & 1;
    const int sA_g = (seg >> 1) & 1;
    const int sB_r = (seg >> 1) & 1;
    const int sB_g = seg & 1;
    const uint32_t a_rowoff = (uint32_t)(wid * 16 + lnx + sA_r * 8) * 128;
    const uint32_t b_rowoff = (uint32_t)(lnx + sB_r * 8) * 128;

    auto doChunk = [&](uint32_t Ab, uint32_t Bb, float* cc) {
        #pragma unroll
        for (int ks = 0; ks < 4; ++ks) {
            uint32_t ag = (uint32_t)(((2 * ks) | sA_g) ^ lnx) << 4;
            uint32_t bg = (uint32_t)(((2 * ks) | sB_g) ^ lnx) << 4;
            uint32_t a0,a1,a2,a3;
            LDSM4(a0,a1,a2,a3, sbase + Ab + a_rowoff + ag);
            #pragma unroll
            for (int jb = 0; jb < 8; ++jb) {
                uint32_t baddr = sbase + Bb + b_rowoff + (uint32_t)(jb * 2048) + bg;
                uint32_t b0,b1,b2,b3;
                LDSM4(b0,b1,b2,b3, baddr);
                float* cp0 = cc + 8 * jb;
                float* cp1 = cc + 8 * jb + 4;
                MMA16816(cp0, a0,a1,a2,a3, b0,b1);
                MMA16816(cp1, a0,a1,a2,a3, b2,b3);
            }
        }
    };

    float c2[64];
    #pragma unroll
    for (int i = 0; i < 64; ++i) c2[i] = 0.0f;

    stageH(0, EO_A0);
    __syncthreads();
    stageH(1, EO_A1);          // LDGs overlap chunk-0 MMAs below

    mb_wait(mb0, 0);
    doChunk(EO_A0, EO_B0, c2);
    __syncthreads();           // A1 fully staged

    mb_wait(mb1, 0);
    doChunk(EO_A1, EO_B1, c2);

    // ============ epilogue: bias, scalar head, register-direct scatter ======
    const int r0 = wid * 16 + (lane >> 2);
    const int q  = lane & 3;
    const int dst0 = sDst[r0];
    const int dst1 = sDst[r0 + 8];
    float w0 = 0.0f, w1 = 0.0f;
    #pragma unroll
    for (int f = 0; f < 16; ++f) {
        int col = 8 * f + 2 * q;
        float2 b  = *(float2*)(sBe2 + col);
        float2 wx = *(float2*)(sWx + col);
        float v0 = c2[4*f+0] + b.x;
        float v1 = c2[4*f+1] + b.y;
        float v2 = c2[4*f+2] + b.x;
        float v3 = c2[4*f+3] + b.y;
        w0 = fmaf(v0, wx.x, fmaf(v1, wx.y, w0));
        w1 = fmaf(v2, wx.x, fmaf(v3, wx.y, w1));
        if (dst0 >= 0) red2(g_mi + (size_t)dst0 * 128 + col, v0, v1);
        if (dst1 >= 0) red2(g_mi + (size_t)dst1 * 128 + col, v2, v3);
    }
    w0 += __shfl_xor_sync(0xffffffffu, w0, 1);
    w0 += __shfl_xor_sync(0xffffffffu, w0, 2);
    w1 += __shfl_xor_sync(0xffffffffu, w1, 1);
    w1 += __shfl_xor_sync(0xffffffffu, w1, 2);
    if (q == 0) {
        sW[r0]     = w0 + bx;
        sW[r0 + 8] = w1 + bx;
    }
    __syncthreads();

    if (t < ETE) {
        int di = sDst[t];
        if (di >= 0) {
            float w = sW[t];
            float4 ds = sDS[t];
            red4(g_dx4 + (size_t)di * 4, make_float4(ds.x * w, ds.y * w, ds.z * w, 0.0f));
        }
    }
}

// ---------------- node kernel: fp16 MMA [node|m_i] @ Wh1 -> relu -> @ Wh2 ---
__global__ __launch_bounds__(512, 1)
void node_kernel(const float* __restrict__ bh1,
                 const float* __restrict__ bh2,
                 float* __restrict__ outH,
                 int N)
{
    extern __shared__ char sm[];
    const uint32_t sbase = smem_u32(sm);

    float* sBh1 = (float*)(sm + NO_BH1);
    float* sBh2 = (float*)(sm + NO_BH2);

    const int t    = threadIdx.x;
    const int wid  = t >> 5;
    const int lane = t & 31;
    const int n0   = blockIdx.x * ET2;

    const uint32_t mb0 = sbase + NO_MB;
    const uint32_t mb1 = sbase + NO_MB + 8;

    if (t == 0) { MB_INIT(mb0, 1); MB_INIT(mb1, 1); }
    if (t < 128) {
        sBh1[t] = bh1[t];
        sBh2[t] = bh2[t];
    }
    __syncthreads();

    if (t == 0) {
        MB_EXPECT(mb0, BCH);
        BULK_G2S(sbase + SO_B0, (const void*)gH1[0], BCH, mb0);
        MB_EXPECT(mb1, BCH);
        BULK_G2S(sbase + SO_B1, (const void*)gH1[1], BCH, mb1);
    }

    const int grow  = t >> 1;
    const int ghalf = t & 1;
    const int grnode = n0 + grow;
    const bool gvalid = grnode < N;
    const int grclamp = gvalid ? grnode : 0;
    const uint32_t g_rowoff = (uint32_t)grow * 128;
    const int      g_rx     = grow & 7;
    const uint32_t g_nsz    = gvalid ? 16u : 0u;

    auto stageN = [&](int c, uint32_t abo) {
        const __half* rp = g_nodeh + (size_t)grclamp * 128 + c * 64 + ghalf * 32;
        #pragma unroll
        for (int u = 0; u < 4; ++u) {
            uint32_t dst = sbase + abo + g_rowoff + (uint32_t)(((ghalf * 4 + u) ^ g_rx) << 4);
            CPA16(dst, rp + u * 8, g_nsz);
        }
        CPA_COMMIT();
    };
    auto stageM = [&](int c, uint32_t abo) {
        const float* rp = g_mi + (size_t)grclamp * 128 + (c - 2) * 64 + ghalf * 32;
        #pragma unroll
        for (int u = 0; u < 4; ++u) {
            uint4 H;
            if (gvalid) {
                float4 v0 = *(const float4*)(rp + u * 8);
                float4 v1 = *(const float4*)(rp + u * 8 + 4);
                H.x = packhf2(v0.x, v0.y);
                H.y = packhf2(v0.z, v0.w);
                H.z = packhf2(v1.x, v1.y);
                H.w = packhf2(v1.z, v1.w);
            } else {
                H = make_uint4(0u, 0u, 0u, 0u);
            }
            uint32_t off = g_rowoff + (uint32_t)(((ghalf * 4 + u) ^ g_rx) << 4);
            *(uint4*)(sm + abo + off) = H;
        }
    };

    const int seg = lane >> 3;
    const int lnx = lane & 7;
    const int sA_r = seg & 1;
    const int sA_g = (seg >> 1) & 1;
    const int sB_r = (seg >> 1) & 1;
    const int sB_g = seg & 1;
    const uint32_t a_rowoff = (uint32_t)(wid * 16 + lnx + sA_r * 8) * 128;
    const uint32_t b_rowoff = (uint32_t)(lnx + sB_r * 8) * 128;

    auto doChunk = [&](uint32_t Ab, uint32_t Bb, float* cc) {
        #pragma unroll
        for (int ks = 0; ks < 4; ++ks) {
            uint32_t ag = (uint32_t)(((2 * ks) | sA_g) ^ lnx) << 4;
            uint32_t bg = (uint32_t)(((2 * ks) | sB_g) ^ lnx) << 4;
            uint32_t a0,a1,a2,a3;
            LDSM4(a0,a1,a2,a3, sbase + Ab + a_rowoff + ag);
            #pragma unroll
            for (int jb = 0; jb < 8; ++jb) {
                uint32_t baddr = sbase + Bb + b_rowoff + (uint32_t)(jb * 2048) + bg;
                uint32_t b0,b1,b2,b3;
                LDSM4(b0,b1,b2,b3, baddr);
                float* cp0 = cc + 8 * jb;
                float* cp1 = cc + 8 * jb + 4;
                MMA16816(cp0, a0,a1,a2,a3, b0,b1);
                MMA16816(cp1, a0,a1,a2,a3, b2,b3);
            }
        }
    };

    float c1[64];
    #pragma unroll
    for (int i = 0; i < 64; ++i) c1[i] = 0.0f;

    stageN(0, SO_A0);
    CPA_WAIT0();
    __syncthreads();

    uint32_t ph0 = 0, ph1 = 0;

    #pragma unroll 1
    for (int c = 0; c < 4; ++c) {
        if (c & 1) { mb_wait(mb1, ph1); ph1 ^= 1; }
        else       { mb_wait(mb0, ph0); ph0 ^= 1; }

        if (c == 0)      stageN(1, SO_A1);
        else if (c == 1) stageM(2, SO_A0);
        else if (c == 2) stageM(3, SO_A1);

        doChunk((c & 1) ? SO_A1 : SO_A0, (c & 1) ? SO_B1 : SO_B0, c1);
        CPA_WAIT0();
        __syncthreads();

        if (t == 0) {
            const void* nsrc = (c == 0) ? (const void*)gH1[2]
                             : (c == 1) ? (const void*)gH1[3]
                             : (c == 2) ? (const void*)gH2[0]
                                        : (const void*)gH2[1];
            uint32_t dst = (c & 1) ? (sbase + SO_B1) : (sbase + SO_B0);
            uint32_t mb  = (c & 1) ? mb1 : mb0;
            MB_EXPECT(mb, BCH);
            BULK_G2S(dst, nsrc, BCH, mb);
        }
    }

    const int r0 = wid * 16 + (lane >> 2);
    const int q  = lane & 3;
    const uint32_t hrow0 = (uint32_t)r0 * 128;
    const int      hrx   = r0 & 7;
    #pragma unroll
    for (int f = 0; f < 16; ++f) {
        int col = 8 * f + 2 * q;
        float2 b = *(float2*)(sBh1 + col);
        float v0 = fmaxf(c1[4*f+0] + b.x, 0.0f);
        float v1 = fmaxf(c1[4*f+1] + b.y, 0.0f);
        float v2 = fmaxf(c1[4*f+2] + b.x, 0.0f);
        float v3 = fmaxf(c1[4*f+3] + b.y, 0.0f);

        uint32_t h01 = packhf2(v0, v1);
        uint32_t h23 = packhf2(v2, v3);

        uint32_t abuf = (col >> 6) ? SO_A1 : SO_A0;
        int kc = col & 63;
        uint32_t off = hrow0 + (uint32_t)((((kc >> 3) ^ hrx) << 4) | ((kc & 7) << 1));
        *(uint32_t*)(sm + abuf + off)        = h01;
        *(uint32_t*)(sm + abuf + off + 1024) = h23;
    }
    __syncwarp();

    float c2[64];
    #pragma unroll
    for (int i = 0; i < 64; ++i) c2[i] = 0.0f;

    mb_wait(mb0, ph0); ph0 ^= 1;
    doChunk(SO_A0, SO_B0, c2);
    mb_wait(mb1, ph1); ph1 ^= 1;
    doChunk(SO_A1, SO_B1, c2);

    const int row0 = n0 + r0;
    const int row1 = row0 + 8;
    #pragma unroll
    for (int f = 0; f < 16; ++f) {
        int col = 8 * f + 2 * q;
        float2 b = *(float2*)(sBh2 + col);
        if (row0 < N) {
            float2 v; v.x = c2[4*f+0] + b.x; v.y = c2[4*f+1] + b.y;
            *(float2*)(outH + (size_t)row0 * Fdim + col) = v;
        }
        if (row1 < N) {
            float2 v; v.x = c2[4*f+2] + b.x; v.y = c2[4*f+3] + b.y;
            *(float2*)(outH + (size_t)row1 * Fdim + col) = v;
        }
    }
}

// ---------------- coordinate update -----------------------------------------
__global__ void x_kernel(const float* __restrict__ coord,
                         float* __restrict__ outX,
                         int n3, float C)
{
    int i = blockIdx.x * blockDim.x + threadIdx.x;
    if (i < n3) {
        int n = i / 3, d = i - n * 3;
        outX[i] = coord[i] + g_dx4[(size_t)n * 4 + d] * C;
    }
}

// ---------------- launch -----------------------------------------------------
extern "C" void kernel_launch(void* const* d_in, const int* in_sizes, int n_in,
                              void* d_out, int out_size)
{
    const float* node  = (const float*)d_in[0];
    const float* coord = (const float*)d_in[1];
    const int*   ei    = (const int*)d_in[2];
    const float* We1   = (const float*)d_in[3];
    const float* be1   = (const float*)d_in[4];
    const float* We2   = (const float*)d_in[5];
    const float* be2   = (const float*)d_in[6];
    const float* Wx    = (const float*)d_in[7];
    const float* bx    = (const float*)d_in[8];
    const float* Wh1   = (const float*)d_in[9];
    const float* bh1   = (const float*)d_in[10];
    const float* Wh2   = (const float*)d_in[11];
    const float* bh2   = (const float*)d_in[12];

    const int N = in_sizes[0] / Fdim;
    const int E = in_sizes[2] / 2;

    float* outH = (float*)d_out;
    float* outX = outH + (size_t)N * Fdim;

    cudaFuncSetAttribute(pq_kernel,   cudaFuncAttributeMaxDynamicSharedMemorySize, PQ_SMEM);
    cudaFuncSetAttribute(edge_kernel, cudaFuncAttributeMaxDynamicSharedMemorySize, EDGE_SMEM);
    cudaFuncSetAttribute(node_kernel, cudaFuncAttributeMaxDynamicSharedMemorySize, NODE_SMEM);

    prep_kernel<<<(98304 + 255) / 256, 256>>>(We1, We2, Wh1, Wh2);
    {
        int n_mi = N * 128;
        zero_kernel<<<(n_mi + 255) / 256, 256>>>(node, n_mi, N * 4);
    }
    {
        int grid = (N + ET2 - 1) / ET2;
        pq_kernel<<<grid, 512, PQ_SMEM>>>(be1, N);
    }
    {
        int grid = (E + ETE - 1) / ETE;
        edge_kernel<<<grid, 256, EDGE_SMEM>>>(coord, ei, We1, be2, Wx, bx, E);
    }
    {
        int grid = (N + ET2 - 1) / ET2;
        node_kernel<<<grid, 512, NODE_SMEM>>>(bh1, bh2, outH, N);
    }
    {
        int n3 = N * 3;
        float C = 1.0f / (float)(N - 1);
        x_kernel<<<(n3 + 255) / 256, 256>>>(coord, outX, n3, C);
    }
}

// round 12
// speedup vs baseline: 1.5519x; 1.0008x over previous
#include <cuda_runtime.h>
#include <cuda_fp16.h>
#include <cstdint>

#define Fdim 128
#define ET2  256              // rows per CTA tile for pq/node kernels
#define MAXN 50000

// ---------------- scratch (static device arrays; allocation-free) ----------
__device__ float g_mi[(size_t)MAXN * 128];        // S = sum of hidden per node (fp32)
__device__ float g_dx4[(size_t)MAXN * 4];         // xyz delta + .w = degree
__device__ __align__(16) __half g_nodeh[(size_t)MAXN * 128];   // fp16 node table
__device__ __align__(16) __half g_Ph[(size_t)MAXN * 128];      // fp16: node@We1_top + be1
__device__ __align__(16) __half g_Qh[(size_t)MAXN * 128];      // fp16: node@We1_bot
// swizzled fp16 weight chunk images: rows=n(128), kc(64)
__device__ __align__(16) __half gB1[4][8192];     // We1 (k chunks 0..3)
__device__ __align__(16) __half gH1[2][8192];     // Wh1_top (k chunks 0..1)
__device__ __align__(16) __half gH2[2][8192];     // Wh2
__device__ __align__(16) __half gW2h[2][8192];    // We2 @ Wh1_bot
__device__ float g_wx2[128];                      // We2 @ Wx
__device__ float g_vb[128];                       // be2 @ Wh1_bot
__device__ float g_cx;                            // be2 . Wx + bx

#define BCH 16384            /* bytes per B chunk */

// ---------------- PTX helpers ----------------------------------------------
__device__ __forceinline__ uint32_t smem_u32(const void* p) {
    uint32_t a;
    asm("{ .reg .u64 t; cvta.to.shared.u64 t, %1; cvt.u32.u64 %0, t; }" : "=r"(a) : "l"(p));
    return a;
}

#define LDSM4(r0, r1, r2, r3, addr) \
    asm volatile("ldmatrix.sync.aligned.m8n8.x4.shared.b16 {%0,%1,%2,%3}, [%4];" \
                 : "=r"(r0), "=r"(r1), "=r"(r2), "=r"(r3) : "r"(addr))

#define MMA16816(cp, a0, a1, a2, a3, b0, b1) \
    asm volatile("mma.sync.aligned.m16n8k16.row.col.f32.f16.f16.f32 " \
                 "{%0,%1,%2,%3},{%4,%5,%6,%7},{%8,%9},{%0,%1,%2,%3};" \
                 : "+f"((cp)[0]), "+f"((cp)[1]), "+f"((cp)[2]), "+f"((cp)[3]) \
                 : "r"(a0), "r"(a1), "r"(a2), "r"(a3), "r"(b0), "r"(b1))

#define MB_INIT(mb, c) asm volatile("mbarrier.init.shared.b64 [%0], %1;" :: "r"(mb), "r"(c) : "memory")
#define MB_EXPECT(mb, b) asm volatile("mbarrier.arrive.expect_tx.shared.b64 _, [%0], %1;" :: "r"(mb), "r"(b) : "memory")
#define BULK_G2S(dst, src, bytes, mb) \
    asm volatile("cp.async.bulk.shared::cluster.global.mbarrier::complete_tx::bytes [%0], [%1], %2, [%3];" \
                 :: "r"(dst), "l"(src), "r"(bytes), "r"(mb) : "memory")

#define CPA16(dst, src, n) \
    asm volatile("cp.async.cg.shared.global [%0], [%1], 16, %2;" :: "r"(dst), "l"(src), "r"(n) : "memory")
#define CPA_COMMIT() asm volatile("cp.async.commit_group;" ::: "memory")
#define CPA_WAIT0()  asm volatile("cp.async.wait_group 0;" ::: "memory")

__device__ __forceinline__ void mb_wait(uint32_t mb, uint32_t parity) {
    uint32_t done;
    asm volatile("{ .reg .pred p; mbarrier.try_wait.parity.acquire.cta.shared::cta.b64 p, [%1], %2; selp.b32 %0, 1, 0, p; }"
                 : "=r"(done) : "r"(mb), "r"(parity) : "memory");
    if (!done) {
        asm volatile("{ .reg .pred P1;\nW%=:\n mbarrier.try_wait.parity.acquire.cta.shared::cta.b64 P1, [%0], %1, 0x989680;\n @P1 bra.uni D%=;\n bra.uni W%=;\nD%=:\n}"
                     :: "r"(mb), "r"(parity) : "memory");
    }
}

__device__ __forceinline__ void red4(float* p, float4 v) {
    asm volatile("red.global.add.v4.f32 [%0], {%1,%2,%3,%4};"
                 :: "l"(p), "f"(v.x), "f"(v.y), "f"(v.z), "f"(v.w) : "memory");
}

__device__ __forceinline__ uint32_t packhf2(float a, float b) {
    uint32_t r;
    asm("cvt.rn.f16x2.f32 %0, %1, %2;" : "=r"(r) : "f"(b), "f"(a));
    return r;
}

// packed half2 helpers on raw uint32 bit patterns
__device__ __forceinline__ uint32_t h2_add(uint32_t a, uint32_t b) {
    uint32_t r;
    asm("add.f16x2 %0, %1, %2;" : "=r"(r) : "r"(a), "r"(b));
    return r;
}
__device__ __forceinline__ uint32_t h2_fma(uint32_t a, uint32_t b, uint32_t c) {
    uint32_t r;
    asm("fma.rn.f16x2 %0, %1, %2, %3;" : "=r"(r) : "r"(a), "r"(b), "r"(c));
    return r;
}
__device__ __forceinline__ uint32_t h2_relu(uint32_t a) {
    uint32_t r;
    asm("max.f16x2 %0, %1, %2;" : "=r"(r) : "r"(a), "r"(0u));
    return r;
}
__device__ __forceinline__ float2 h2_unpack(uint32_t h) {
    float2 r;
    asm("{ .reg .b16 lo, hi; mov.b32 {lo, hi}, %2; cvt.f32.f16 %0, lo; cvt.f32.f16 %1, hi; }"
        : "=f"(r.x), "=f"(r.y) : "r"(h));
    return r;
}

// swizzled element offset within a [row][kc] tile, 64 fp16 per row (128 B)
__host__ __device__ __forceinline__ int swoff(int n, int kc) {
    return n * 64 + ((((kc >> 3) ^ (n & 7)) << 3) | (kc & 7));
}

// ---------------- prep: swizzled fp16 weight chunk images -------------------
__global__ void prep_kernel(const float* __restrict__ We1,
                            const float* __restrict__ Wh1,
                            const float* __restrict__ Wh2)
{
    int id = blockIdx.x * blockDim.x + threadIdx.x;
    if (id < 32768) {                               // We1 4 chunks
        int c = id >> 13, rem = id & 8191, n = rem >> 6, kc = rem & 63;
        gB1[c][swoff(n, kc)] = __float2half_rn(We1[(size_t)(c * 64 + kc) * 128 + n]);
    } else if (id < 49152) {                        // Wh1_top 2 chunks
        int id2 = id - 32768;
        int c = id2 >> 13, rem = id2 & 8191, n = rem >> 6, kc = rem & 63;
        gH1[c][swoff(n, kc)] = __float2half_rn(Wh1[(size_t)(c * 64 + kc) * 128 + n]);
    } else if (id < 65536) {                        // Wh2 2 chunks
        int id2 = id - 49152;
        int c = id2 >> 13, rem = id2 & 8191, n = rem >> 6, kc = rem & 63;
        gH2[c][swoff(n, kc)] = __float2half_rn(Wh2[(size_t)(c * 64 + kc) * 128 + n]);
    }
}

// ---------------- prep2: folded-weight products -------------------------------
// W2h = We2 @ Wh1_bot ; wx2 = We2 @ Wx ; vb = be2 @ Wh1_bot ; cx = be2.Wx + bx
__global__ void prep2_kernel(const float* __restrict__ We2,
                             const float* __restrict__ Wh1,
                             const float* __restrict__ Wx,
                             const float* __restrict__ be2,
                             const float* __restrict__ bxp)
{
    int id = blockIdx.x * blockDim.x + threadIdx.x;
    if (id < 16384) {
        int c  = id >> 13;
        int rem = id & 8191;
        int kc = rem >> 7;          // 0..63
        int n  = rem & 127;         // coalesced across lanes
        int k  = c * 64 + kc;
        float acc = 0.0f;
        #pragma unroll 4
        for (int j = 0; j < 128; ++j)
            acc = fmaf(We2[(size_t)k * 128 + j], Wh1[(size_t)(128 + j) * 128 + n], acc);
        gW2h[c][swoff(n, kc)] = __float2half_rn(acc);
    } else if (id < 16512) {
        int k = id - 16384;
        float acc = 0.0f;
        for (int j = 0; j < 128; ++j)
            acc = fmaf(We2[(size_t)k * 128 + j], Wx[j], acc);
        g_wx2[k] = acc;
    } else if (id < 16640) {
        int n = id - 16512;
        float acc = 0.0f;
        for (int j = 0; j < 128; ++j)
            acc = fmaf(be2[j], Wh1[(size_t)(128 + j) * 128 + n], acc);
        g_vb[n] = acc;
    } else if (id == 16640) {
        float acc = bxp[0];
        for (int j = 0; j < 128; ++j)
            acc = fmaf(be2[j], Wx[j], acc);
        g_cx = acc;
    }
}

// ---------------- zero scratch + convert node table to fp16 -----------------
__global__ void zero_kernel(const float* __restrict__ node, int n_mi, int n_dx)
{
    int i = blockIdx.x * blockDim.x + threadIdx.x;
    if (i < n_mi) {
        g_mi[i] = 0.0f;
        g_nodeh[i] = __float2half_rn(node[i]);
    }
    if (i < n_dx) g_dx4[i] = 0.0f;
}

// ---------------- SMEM layouts for pq / node kernels -------------------------
#define SO_A0   0
#define SO_A1   32768
#define SO_B0   65536
#define SO_B1   81920
#define PQ_BE1  98304
#define PQ_MB   98816
#define PQ_SMEM 98848
#define NO_BH1  98304
#define NO_BH2  98816
#define NO_VB   99328
#define NO_MB   99840
#define NODE_SMEM 99872

// ---------------- PQ precompute: P = node@W_top + be1 ; Q = node@W_bot ------
__global__ __launch_bounds__(512, 1)
void pq_kernel(const float* __restrict__ be1, int N)
{
    extern __shared__ char sm[];
    const uint32_t sbase = smem_u32(sm);
    float* sBe1 = (float*)(sm + PQ_BE1);

    const int t    = threadIdx.x;
    const int wid  = t >> 5;
    const int lane = t & 31;
    const int n0   = blockIdx.x * ET2;

    const uint32_t mb0 = sbase + PQ_MB;
    const uint32_t mb1 = sbase + PQ_MB + 8;

    if (t == 0) { MB_INIT(mb0, 1); MB_INIT(mb1, 1); }
    if (t < 128) sBe1[t] = be1[t];
    __syncthreads();

    if (t == 0) {
        MB_EXPECT(mb0, BCH);
        BULK_G2S(sbase + SO_B0, (const void*)gB1[0], BCH, mb0);
        MB_EXPECT(mb1, BCH);
        BULK_G2S(sbase + SO_B1, (const void*)gB1[1], BCH, mb1);
    }

    const int grow  = t >> 1;
    const int ghalf = t & 1;
    const int grnode = n0 + grow;
    const bool gvalid = grnode < N;
    const int grclamp = gvalid ? grnode : 0;
    const uint32_t g_rowoff = (uint32_t)grow * 128;
    const int      g_rx     = grow & 7;
    const uint32_t g_nsz    = gvalid ? 16u : 0u;

    auto stageN = [&](int c, uint32_t abo) {
        const __half* rp = g_nodeh + (size_t)grclamp * 128 + c * 64 + ghalf * 32;
        #pragma unroll
        for (int u = 0; u < 4; ++u) {
            uint32_t dst = sbase + abo + g_rowoff + (uint32_t)(((ghalf * 4 + u) ^ g_rx) << 4);
            CPA16(dst, rp + u * 8, g_nsz);
        }
        CPA_COMMIT();
    };

    const int seg = lane >> 3;
    const int lnx = lane & 7;
    const int sA_r = seg & 1;
    const int sA_g = (seg >> 1) & 1;
    const int sB_r = (seg >> 1) & 1;
    const int sB_g = seg & 1;
    const uint32_t a_rowoff = (uint32_t)(wid * 16 + lnx + sA_r * 8) * 128;
    const uint32_t b_rowoff = (uint32_t)(lnx + sB_r * 8) * 128;

    auto doChunk = [&](uint32_t Ab, uint32_t Bb, float* cc) {
        #pragma unroll
        for (int ks = 0; ks < 4; ++ks) {
            uint32_t ag = (uint32_t)(((2 * ks) | sA_g) ^ lnx) << 4;
            uint32_t bg = (uint32_t)(((2 * ks) | sB_g) ^ lnx) << 4;
            uint32_t a0,a1,a2,a3;
            LDSM4(a0,a1,a2,a3, sbase + Ab + a_rowoff + ag);
            #pragma unroll
            for (int jb = 0; jb < 8; ++jb) {
                uint32_t baddr = sbase + Bb + b_rowoff + (uint32_t)(jb * 2048) + bg;
                uint32_t b0,b1,b2,b3;
                LDSM4(b0,b1,b2,b3, baddr);
                float* cp0 = cc + 8 * jb;
                float* cp1 = cc + 8 * jb + 4;
                MMA16816(cp0, a0,a1,a2,a3, b0,b1);
                MMA16816(cp1, a0,a1,a2,a3, b2,b3);
            }
        }
    };

    float cc[64];
    #pragma unroll
    for (int i = 0; i < 64; ++i) cc[i] = 0.0f;

    stageN(0, SO_A0);
    stageN(1, SO_A1);
    CPA_WAIT0();
    __syncthreads();

    // P pass: A0@gB1[0] + A1@gB1[1]
    mb_wait(mb0, 0);
    doChunk(SO_A0, SO_B0, cc);
    __syncthreads();
    if (t == 0) { MB_EXPECT(mb0, BCH); BULK_G2S(sbase + SO_B0, (const void*)gB1[2], BCH, mb0); }
    mb_wait(mb1, 0);
    doChunk(SO_A1, SO_B1, cc);
    __syncthreads();
    if (t == 0) { MB_EXPECT(mb1, BCH); BULK_G2S(sbase + SO_B1, (const void*)gB1[3], BCH, mb1); }

    const int r0 = wid * 16 + (lane >> 2);
    const int q  = lane & 3;
    const int row0 = n0 + r0;
    const int row1 = row0 + 8;

    #pragma unroll
    for (int f = 0; f < 16; ++f) {
        int col = 8 * f + 2 * q;
        float2 b = *(float2*)(sBe1 + col);
        if (row0 < N)
            *(uint32_t*)(g_Ph + (size_t)row0 * 128 + col) = packhf2(cc[4*f+0] + b.x, cc[4*f+1] + b.y);
        if (row1 < N)
            *(uint32_t*)(g_Ph + (size_t)row1 * 128 + col) = packhf2(cc[4*f+2] + b.x, cc[4*f+3] + b.y);
    }

    // Q pass: A0@gB1[2] + A1@gB1[3]
    #pragma unroll
    for (int i = 0; i < 64; ++i) cc[i] = 0.0f;
    mb_wait(mb0, 1);
    doChunk(SO_A0, SO_B0, cc);
    mb_wait(mb1, 1);
    doChunk(SO_A1, SO_B1, cc);

    #pragma unroll
    for (int f = 0; f < 16; ++f) {
        int col = 8 * f + 2 * q;
        if (row0 < N)
            *(uint32_t*)(g_Qh + (size_t)row0 * 128 + col) = packhf2(cc[4*f+0], cc[4*f+1]);
        if (row1 < N)
            *(uint32_t*)(g_Qh + (size_t)row1 * 128 + col) = packhf2(cc[4*f+2], cc[4*f+3]);
    }
}

// ---------------- edge kernel: no MMA ----------------------------------------
// hidden = relu(P[dst]+Q[src]+sq*w256); scatter hidden (fp32) to g_mi[dst];
// w = hidden . wx2 + cx; scatter (dist*w, 1) to g_dx4[dst].
// 256 threads, 64 edges per block, 4 threads per edge.
__global__ __launch_bounds__(256, 4)
void edge_kernel(const float* __restrict__ coord,
                 const int*   __restrict__ ei,
                 const float* __restrict__ We1,
                 int E)
{
    __shared__ float4 sDS[64];
    __shared__ int    sDst[64];
    __shared__ int    sSrc[64];
    __shared__ __half sW256[128];
    __shared__ float  sWx2[128];

    const int t  = threadIdx.x;
    const int e0 = blockIdx.x * 64;

    if (t < 64) {
        int eg = e0 + t;
        float dx = 0.f, dy = 0.f, dz = 0.f;
        int di = -1, si = 0;
        if (eg < E) {
            si = ei[eg];
            di = ei[E + eg];
            dx = coord[(size_t)di * 3 + 0] - coord[(size_t)si * 3 + 0];
            dy = coord[(size_t)di * 3 + 1] - coord[(size_t)si * 3 + 1];
            dz = coord[(size_t)di * 3 + 2] - coord[(size_t)si * 3 + 2];
        }
        sDS[t]  = make_float4(dx, dy, dz, dx * dx + dy * dy + dz * dz);
        sDst[t] = di;
        sSrc[t] = si;
    }
    if (t < 128) {
        sW256[t] = __float2half_rn(We1[(size_t)256 * 128 + t]);
        sWx2[t]  = g_wx2[t];
    }
    __syncthreads();

    const int e = t >> 2;
    const int q = t & 3;
    const int di = sDst[e];
    const int si = sSrc[e];
    const bool valid = (di >= 0);
    const int dic = valid ? di : 0;
    const int sic = valid ? si : 0;
    const float4 ds = sDS[e];
    const uint32_t sq2 = packhf2(ds.w, ds.w);

    const uint4* pp = (const uint4*)(g_Ph + (size_t)dic * 128 + q * 32);
    const uint4* qq = (const uint4*)(g_Qh + (size_t)sic * 128 + q * 32);
    const uint4* ww = (const uint4*)sW256 + q * 4;
    float* sc = g_mi + (size_t)dic * 128 + q * 32;
    const float* wxp = sWx2 + q * 32;

    float w = 0.0f;
    #pragma unroll
    for (int u = 0; u < 4; ++u) {
        uint4 P = pp[u];
        uint4 Q = qq[u];
        uint4 W = ww[u];
        uint32_t h0 = h2_relu(h2_fma(sq2, W.x, h2_add(P.x, Q.x)));
        uint32_t h1 = h2_relu(h2_fma(sq2, W.y, h2_add(P.y, Q.y)));
        uint32_t h2v = h2_relu(h2_fma(sq2, W.z, h2_add(P.z, Q.z)));
        uint32_t h3 = h2_relu(h2_fma(sq2, W.w, h2_add(P.w, Q.w)));
        float2 f0 = h2_unpack(h0);
        float2 f1 = h2_unpack(h1);
        float2 f2 = h2_unpack(h2v);
        float2 f3 = h2_unpack(h3);
        const float* wx = wxp + u * 8;
        w = fmaf(f0.x, wx[0], w); w = fmaf(f0.y, wx[1], w);
        w = fmaf(f1.x, wx[2], w); w = fmaf(f1.y, wx[3], w);
        w = fmaf(f2.x, wx[4], w); w = fmaf(f2.y, wx[5], w);
        w = fmaf(f3.x, wx[6], w); w = fmaf(f3.y, wx[7], w);
        if (valid) {
            red4(sc + u * 8,     make_float4(f0.x, f0.y, f1.x, f1.y));
            red4(sc + u * 8 + 4, make_float4(f2.x, f2.y, f3.x, f3.y));
        }
    }

    // reduce w over the quad
    w += __shfl_xor_sync(0xffffffffu, w, 1);
    w += __shfl_xor_sync(0xffffffffu, w, 2);
    if (q == 0 && valid) {
        float wf = w + g_cx;
        red4(g_dx4 + (size_t)di * 4,
             make_float4(ds.x * wf, ds.y * wf, ds.z * wf, 1.0f));
    }
}

// ---------------- node kernel: h_new = relu([node|S]@[Wh1_top;W2h] + deg*vb + bh1)@Wh2 + bh2
__global__ __launch_bounds__(512, 1)
void node_kernel(const float* __restrict__ bh1,
                 const float* __restrict__ bh2,
                 float* __restrict__ outH,
                 int N)
{
    extern __shared__ char sm[];
    const uint32_t sbase = smem_u32(sm);

    float* sBh1 = (float*)(sm + NO_BH1);
    float* sBh2 = (float*)(sm + NO_BH2);
    float* sVb  = (float*)(sm + NO_VB);

    const int t    = threadIdx.x;
    const int wid  = t >> 5;
    const int lane = t & 31;
    const int n0   = blockIdx.x * ET2;

    const uint32_t mb0 = sbase + NO_MB;
    const uint32_t mb1 = sbase + NO_MB + 8;

    if (t == 0) { MB_INIT(mb0, 1); MB_INIT(mb1, 1); }
    if (t < 128) {
        sBh1[t] = bh1[t];
        sBh2[t] = bh2[t];
        sVb[t]  = g_vb[t];
    }
    __syncthreads();

    if (t == 0) {
        MB_EXPECT(mb0, BCH);
        BULK_G2S(sbase + SO_B0, (const void*)gH1[0], BCH, mb0);
        MB_EXPECT(mb1, BCH);
        BULK_G2S(sbase + SO_B1, (const void*)gH1[1], BCH, mb1);
    }

    const int grow  = t >> 1;
    const int ghalf = t & 1;
    const int grnode = n0 + grow;
    const bool gvalid = grnode < N;
    const int grclamp = gvalid ? grnode : 0;
    const uint32_t g_rowoff = (uint32_t)grow * 128;
    const int      g_rx     = grow & 7;
    const uint32_t g_nsz    = gvalid ? 16u : 0u;

    auto stageN = [&](int c, uint32_t abo) {
        const __half* rp = g_nodeh + (size_t)grclamp * 128 + c * 64 + ghalf * 32;
        #pragma unroll
        for (int u = 0; u < 4; ++u) {
            uint32_t dst = sbase + abo + g_rowoff + (uint32_t)(((ghalf * 4 + u) ^ g_rx) << 4);
            CPA16(dst, rp + u * 8, g_nsz);
        }
        CPA_COMMIT();
    };
    auto stageM = [&](int c, uint32_t abo) {
        const float* rp = g_mi + (size_t)grclamp * 128 + (c - 2) * 64 + ghalf * 32;
        #pragma unroll
        for (int u = 0; u < 4; ++u) {
            uint4 H;
            if (gvalid) {
                float4 v0 = *(const float4*)(rp + u * 8);
                float4 v1 = *(const float4*)(rp + u * 8 + 4);
                H.x = packhf2(v0.x, v0.y);
                H.y = packhf2(v0.z, v0.w);
                H.z = packhf2(v1.x, v1.y);
                H.w = packhf2(v1.z, v1.w);
            } else {
                H = make_uint4(0u, 0u, 0u, 0u);
            }
            uint32_t off = g_rowoff + (uint32_t)(((ghalf * 4 + u) ^ g_rx) << 4);
            *(uint4*)(sm + abo + off) = H;
        }
    };

    const int seg = lane >> 3;
    const int lnx = lane & 7;
    const int sA_r = seg & 1;
    const int sA_g = (seg >> 1) & 1;
    const int sB_r = (seg >> 1) & 1;
    const int sB_g = seg & 1;
    const uint32_t a_rowoff = (uint32_t)(wid * 16 + lnx + sA_r * 8) * 128;
    const uint32_t b_rowoff = (uint32_t)(lnx + sB_r * 8) * 128;

    auto doChunk = [&](uint32_t Ab, uint32_t Bb, float* cc) {
        #pragma unroll
        for (int ks = 0; ks < 4; ++ks) {
            uint32_t ag = (uint32_t)(((2 * ks) | sA_g) ^ lnx) << 4;
            uint32_t bg = (uint32_t)(((2 * ks) | sB_g) ^ lnx) << 4;
            uint32_t a0,a1,a2,a3;
            LDSM4(a0,a1,a2,a3, sbase + Ab + a_rowoff + ag);
            #pragma unroll
            for (int jb = 0; jb < 8; ++jb) {
                uint32_t baddr = sbase + Bb + b_rowoff + (uint32_t)(jb * 2048) + bg;
                uint32_t b0,b1,b2,b3;
                LDSM4(b0,b1,b2,b3, baddr);
                float* cp0 = cc + 8 * jb;
                float* cp1 = cc + 8 * jb + 4;
                MMA16816(cp0, a0,a1,a2,a3, b0,b1);
                MMA16816(cp1, a0,a1,a2,a3, b2,b3);
            }
        }
    };

    float c1[64];
    #pragma unroll
    for (int i = 0; i < 64; ++i) c1[i] = 0.0f;

    stageN(0, SO_A0);
    CPA_WAIT0();
    __syncthreads();

    uint32_t ph0 = 0, ph1 = 0;

    #pragma unroll 1
    for (int c = 0; c < 4; ++c) {
        if (c & 1) { mb_wait(mb1, ph1); ph1 ^= 1; }
        else       { mb_wait(mb0, ph0); ph0 ^= 1; }

        if (c == 0)      stageN(1, SO_A1);
        else if (c == 1) stageM(2, SO_A0);
        else if (c == 2) stageM(3, SO_A1);

        doChunk((c & 1) ? SO_A1 : SO_A0, (c & 1) ? SO_B1 : SO_B0, c1);
        CPA_WAIT0();
        __syncthreads();

        if (t == 0) {
            const void* nsrc = (c == 0) ? (const void*)gW2h[0]
                             : (c == 1) ? (const void*)gW2h[1]
                             : (c == 2) ? (const void*)gH2[0]
                                        : (const void*)gH2[1];
            uint32_t dst = (c & 1) ? (sbase + SO_B1) : (sbase + SO_B0);
            uint32_t mb  = (c & 1) ? mb1 : mb0;
            MB_EXPECT(mb, BCH);
            BULK_G2S(dst, nsrc, BCH, mb);
        }
    }

    const int r0 = wid * 16 + (lane >> 2);
    const int q  = lane & 3;
    const int row0 = n0 + r0;
    const int row1 = row0 + 8;
    const float deg0 = (row0 < N) ? g_dx4[(size_t)row0 * 4 + 3] : 0.0f;
    const float deg1 = (row1 < N) ? g_dx4[(size_t)row1 * 4 + 3] : 0.0f;

    const uint32_t hrow0 = (uint32_t)r0 * 128;
    const int      hrx   = r0 & 7;
    #pragma unroll
    for (int f = 0; f < 16; ++f) {
        int col = 8 * f + 2 * q;
        float2 b  = *(float2*)(sBh1 + col);
        float2 vb = *(float2*)(sVb + col);
        float v0 = fmaxf(c1[4*f+0] + b.x + deg0 * vb.x, 0.0f);
        float v1 = fmaxf(c1[4*f+1] + b.y + deg0 * vb.y, 0.0f);
        float v2 = fmaxf(c1[4*f+2] + b.x + deg1 * vb.x, 0.0f);
        float v3 = fmaxf(c1[4*f+3] + b.y + deg1 * vb.y, 0.0f);

        uint32_t h01 = packhf2(v0, v1);
        uint32_t h23 = packhf2(v2, v3);

        uint32_t abuf = (col >> 6) ? SO_A1 : SO_A0;
        int kc = col & 63;
        uint32_t off = hrow0 + (uint32_t)((((kc >> 3) ^ hrx) << 4) | ((kc & 7) << 1));
        *(uint32_t*)(sm + abuf + off)        = h01;
        *(uint32_t*)(sm + abuf + off + 1024) = h23;
    }
    __syncwarp();

    float c2[64];
    #pragma unroll
    for (int i = 0; i < 64; ++i) c2[i] = 0.0f;

    mb_wait(mb0, ph0); ph0 ^= 1;
    doChunk(SO_A0, SO_B0, c2);
    mb_wait(mb1, ph1); ph1 ^= 1;
    doChunk(SO_A1, SO_B1, c2);

    #pragma unroll
    for (int f = 0; f < 16; ++f) {
        int col = 8 * f + 2 * q;
        float2 b = *(float2*)(sBh2 + col);
        if (row0 < N) {
            float2 v; v.x = c2[4*f+0] + b.x; v.y = c2[4*f+1] + b.y;
            *(float2*)(outH + (size_t)row0 * Fdim + col) = v;
        }
        if (row1 < N) {
            float2 v; v.x = c2[4*f+2] + b.x; v.y = c2[4*f+3] + b.y;
            *(float2*)(outH + (size_t)row1 * Fdim + col) = v;
        }
    }
}

// ---------------- coordinate update -----------------------------------------
__global__ void x_kernel(const float* __restrict__ coord,
                         float* __restrict__ outX,
                         int n3, float C)
{
    int i = blockIdx.x * blockDim.x + threadIdx.x;
    if (i < n3) {
        int n = i / 3, d = i - n * 3;
        outX[i] = coord[i] + g_dx4[(size_t)n * 4 + d] * C;
    }
}

// ---------------- launch -----------------------------------------------------
extern "C" void kernel_launch(void* const* d_in, const int* in_sizes, int n_in,
                              void* d_out, int out_size)
{
    const float* node  = (const float*)d_in[0];
    const float* coord = (const float*)d_in[1];
    const int*   ei    = (const int*)d_in[2];
    const float* We1   = (const float*)d_in[3];
    const float* be1   = (const float*)d_in[4];
    const float* We2   = (const float*)d_in[5];
    const float* be2   = (const float*)d_in[6];
    const float* Wx    = (const float*)d_in[7];
    const float* bx    = (const float*)d_in[8];
    const float* Wh1   = (const float*)d_in[9];
    const float* bh1   = (const float*)d_in[10];
    const float* Wh2   = (const float*)d_in[11];
    const float* bh2   = (const float*)d_in[12];

    const int N = in_sizes[0] / Fdim;
    const int E = in_sizes[2] / 2;

    float* outH = (float*)d_out;
    float* outX = outH + (size_t)N * Fdim;

    cudaFuncSetAttribute(pq_kernel,   cudaFuncAttributeMaxDynamicSharedMemorySize, PQ_SMEM);
    cudaFuncSetAttribute(node_kernel, cudaFuncAttributeMaxDynamicSharedMemorySize, NODE_SMEM);

    prep_kernel<<<(65536 + 255) / 256, 256>>>(We1, Wh1, Wh2);
    prep2_kernel<<<(16641 + 255) / 256, 256>>>(We2, Wh1, Wx, be2, bx);
    {
        int n_mi = N * 128;
        zero_kernel<<<(n_mi + 255) / 256, 256>>>(node, n_mi, N * 4);
    }
    {
        int grid = (N + ET2 - 1) / ET2;
        pq_kernel<<<grid, 512, PQ_SMEM>>>(be1, N);
    }
    {
        int grid = (E + 63) / 64;
        edge_kernel<<<grid, 256>>>(coord, ei, We1, E);
    }
    {
        int grid = (N + ET2 - 1) / ET2;
        node_kernel<<<grid, 512, NODE_SMEM>>>(bh1, bh2, outH, N);
    }
    {
        int n3 = N * 3;
        float C = 1.0f / (float)(N - 1);
        x_kernel<<<(n3 + 255) / 256, 256>>>(coord, outX, n3, C);
    }
}

// round 13
// speedup vs baseline: 1.8535x; 1.1944x over previous
#include <cuda_runtime.h>
#include <cuda_fp16.h>
#include <cstdint>

#define Fdim 128
#define ET2  256              // rows per CTA tile for pq/node kernels
#define MAXN 50000
#define MAXE 800000

// ---------------- scratch (static device arrays; allocation-free) ----------
__device__ float g_mi[(size_t)MAXN * 128];        // S = sum of hidden per node (fp32)
__device__ float g_dx4[(size_t)MAXN * 4];         // xyz delta + .w = degree
__device__ __align__(16) __half g_nodeh[(size_t)MAXN * 128];   // fp16 node table
__device__ __align__(16) __half g_Ph[(size_t)MAXN * 128];      // fp16: node@We1_top + be1
__device__ __align__(16) __half g_Qh[(size_t)MAXN * 128];      // fp16: node@We1_bot
// CSR (dst -> incoming edges)
__device__ int g_cnt[MAXN];
__device__ int g_cur[MAXN];
__device__ int g_rowptr[MAXN + 1];
__device__ int g_csr[MAXE];
// swizzled fp16 weight chunk images: rows=n(128), kc(64)
__device__ __align__(16) __half gB1[4][8192];     // We1 (k chunks 0..3)
__device__ __align__(16) __half gH1[2][8192];     // Wh1_top (k chunks 0..1)
__device__ __align__(16) __half gH2[2][8192];     // Wh2
__device__ __align__(16) __half gW2h[2][8192];    // We2 @ Wh1_bot
__device__ float g_wx2[128];                      // We2 @ Wx
__device__ float g_vb[128];                       // be2 @ Wh1_bot
__device__ float g_cx;                            // be2 . Wx + bx

#define BCH 16384            /* bytes per B chunk */

// ---------------- PTX helpers ----------------------------------------------
__device__ __forceinline__ uint32_t smem_u32(const void* p) {
    uint32_t a;
    asm("{ .reg .u64 t; cvta.to.shared.u64 t, %1; cvt.u32.u64 %0, t; }" : "=r"(a) : "l"(p));
    return a;
}

#define LDSM4(r0, r1, r2, r3, addr) \
    asm volatile("ldmatrix.sync.aligned.m8n8.x4.shared.b16 {%0,%1,%2,%3}, [%4];" \
                 : "=r"(r0), "=r"(r1), "=r"(r2), "=r"(r3) : "r"(addr))

#define MMA16816(cp, a0, a1, a2, a3, b0, b1) \
    asm volatile("mma.sync.aligned.m16n8k16.row.col.f32.f16.f16.f32 " \
                 "{%0,%1,%2,%3},{%4,%5,%6,%7},{%8,%9},{%0,%1,%2,%3};" \
                 : "+f"((cp)[0]), "+f"((cp)[1]), "+f"((cp)[2]), "+f"((cp)[3]) \
                 : "r"(a0), "r"(a1), "r"(a2), "r"(a3), "r"(b0), "r"(b1))

#define MB_INIT(mb, c) asm volatile("mbarrier.init.shared.b64 [%0], %1;" :: "r"(mb), "r"(c) : "memory")
#define MB_EXPECT(mb, b) asm volatile("mbarrier.arrive.expect_tx.shared.b64 _, [%0], %1;" :: "r"(mb), "r"(b) : "memory")
#define BULK_G2S(dst, src, bytes, mb) \
    asm volatile("cp.async.bulk.shared::cluster.global.mbarrier::complete_tx::bytes [%0], [%1], %2, [%3];" \
                 :: "r"(dst), "l"(src), "r"(bytes), "r"(mb) : "memory")

#define CPA16(dst, src, n) \
    asm volatile("cp.async.cg.shared.global [%0], [%1], 16, %2;" :: "r"(dst), "l"(src), "r"(n) : "memory")
#define CPA_COMMIT() asm volatile("cp.async.commit_group;" ::: "memory")
#define CPA_WAIT0()  asm volatile("cp.async.wait_group 0;" ::: "memory")

__device__ __forceinline__ void mb_wait(uint32_t mb, uint32_t parity) {
    uint32_t done;
    asm volatile("{ .reg .pred p; mbarrier.try_wait.parity.acquire.cta.shared::cta.b64 p, [%1], %2; selp.b32 %0, 1, 0, p; }"
                 : "=r"(done) : "r"(mb), "r"(parity) : "memory");
    if (!done) {
        asm volatile("{ .reg .pred P1;\nW%=:\n mbarrier.try_wait.parity.acquire.cta.shared::cta.b64 P1, [%0], %1, 0x989680;\n @P1 bra.uni D%=;\n bra.uni W%=;\nD%=:\n}"
                     :: "r"(mb), "r"(parity) : "memory");
    }
}

__device__ __forceinline__ uint32_t packhf2(float a, float b) {
    uint32_t r;
    asm("cvt.rn.f16x2.f32 %0, %1, %2;" : "=r"(r) : "f"(b), "f"(a));
    return r;
}

// packed half2 helpers on raw uint32 bit patterns
__device__ __forceinline__ uint32_t h2_add(uint32_t a, uint32_t b) {
    uint32_t r;
    asm("add.f16x2 %0, %1, %2;" : "=r"(r) : "r"(a), "r"(b));
    return r;
}
__device__ __forceinline__ uint32_t h2_fma(uint32_t a, uint32_t b, uint32_t c) {
    uint32_t r;
    asm("fma.rn.f16x2 %0, %1, %2, %3;" : "=r"(r) : "r"(a), "r"(b), "r"(c));
    return r;
}
__device__ __forceinline__ uint32_t h2_relu(uint32_t a) {
    uint32_t r;
    asm("max.f16x2 %0, %1, %2;" : "=r"(r) : "r"(a), "r"(0u));
    return r;
}
__device__ __forceinline__ float2 h2_unpack(uint32_t h) {
    float2 r;
    asm("{ .reg .b16 lo, hi; mov.b32 {lo, hi}, %2; cvt.f32.f16 %0, lo; cvt.f32.f16 %1, hi; }"
        : "=f"(r.x), "=f"(r.y) : "r"(h));
    return r;
}

// swizzled element offset within a [row][kc] tile, 64 fp16 per row (128 B)
__host__ __device__ __forceinline__ int swoff(int n, int kc) {
    return n * 64 + ((((kc >> 3) ^ (n & 7)) << 3) | (kc & 7));
}

// ---------------- prep: swizzled fp16 weight chunk images -------------------
__global__ void prep_kernel(const float* __restrict__ We1,
                            const float* __restrict__ Wh1,
                            const float* __restrict__ Wh2)
{
    int id = blockIdx.x * blockDim.x + threadIdx.x;
    if (id < 32768) {                               // We1 4 chunks
        int c = id >> 13, rem = id & 8191, n = rem >> 6, kc = rem & 63;
        gB1[c][swoff(n, kc)] = __float2half_rn(We1[(size_t)(c * 64 + kc) * 128 + n]);
    } else if (id < 49152) {                        // Wh1_top 2 chunks
        int id2 = id - 32768;
        int c = id2 >> 13, rem = id2 & 8191, n = rem >> 6, kc = rem & 63;
        gH1[c][swoff(n, kc)] = __float2half_rn(Wh1[(size_t)(c * 64 + kc) * 128 + n]);
    } else if (id < 65536) {                        // Wh2 2 chunks
        int id2 = id - 49152;
        int c = id2 >> 13, rem = id2 & 8191, n = rem >> 6, kc = rem & 63;
        gH2[c][swoff(n, kc)] = __float2half_rn(Wh2[(size_t)(c * 64 + kc) * 128 + n]);
    }
}

// ---------------- prep2: folded-weight products -------------------------------
__global__ void prep2_kernel(const float* __restrict__ We2,
                             const float* __restrict__ Wh1,
                             const float* __restrict__ Wx,
                             const float* __restrict__ be2,
                             const float* __restrict__ bxp)
{
    int id = blockIdx.x * blockDim.x + threadIdx.x;
    if (id < 16384) {
        int c  = id >> 13;
        int rem = id & 8191;
        int kc = rem >> 7;
        int n  = rem & 127;
        int k  = c * 64 + kc;
        float acc = 0.0f;
        #pragma unroll 4
        for (int j = 0; j < 128; ++j)
            acc = fmaf(We2[(size_t)k * 128 + j], Wh1[(size_t)(128 + j) * 128 + n], acc);
        gW2h[c][swoff(n, kc)] = __float2half_rn(acc);
    } else if (id < 16512) {
        int k = id - 16384;
        float acc = 0.0f;
        for (int j = 0; j < 128; ++j)
            acc = fmaf(We2[(size_t)k * 128 + j], Wx[j], acc);
        g_wx2[k] = acc;
    } else if (id < 16640) {
        int n = id - 16512;
        float acc = 0.0f;
        for (int j = 0; j < 128; ++j)
            acc = fmaf(be2[j], Wh1[(size_t)(128 + j) * 128 + n], acc);
        g_vb[n] = acc;
    } else if (id == 16640) {
        float acc = bxp[0];
        for (int j = 0; j < 128; ++j)
            acc = fmaf(be2[j], Wx[j], acc);
        g_cx = acc;
    }
}

// ---------------- zero: convert node table + clear CSR counters -------------
__global__ void zero_kernel(const float* __restrict__ node, int n_mi, int N)
{
    int i = blockIdx.x * blockDim.x + threadIdx.x;
    if (i < n_mi) g_nodeh[i] = __float2half_rn(node[i]);
    if (i < N) g_cnt[i] = 0;
}

// ---------------- CSR build ---------------------------------------------------
__global__ void hist_kernel(const int* __restrict__ ei, int E)
{
    int i = blockIdx.x * blockDim.x + threadIdx.x;
    if (i < E) atomicAdd(&g_cnt[ei[E + i]], 1);
}

__global__ void scan_kernel(int N)
{
    __shared__ int ssum[1024];
    const int t = threadIdx.x;
    const int CH = (N + 1023) / 1024;
    const int b = t * CH;
    const int e = min(b + CH, N);
    int s = 0;
    for (int i = b; i < e; ++i) s += g_cnt[i];
    ssum[t] = s;
    __syncthreads();
    for (int off = 1; off < 1024; off <<= 1) {
        int v = (t >= off) ? ssum[t - off] : 0;
        __syncthreads();
        ssum[t] += v;
        __syncthreads();
    }
    int base = ssum[t] - s;       // exclusive prefix
    for (int i = b; i < e; ++i) {
        int c = g_cnt[i];
        g_rowptr[i] = base;
        g_cur[i]    = base;
        base += c;
    }
    if (t == 1023) g_rowptr[N] = base;
}

__global__ void place_kernel(const int* __restrict__ ei, int E)
{
    int i = blockIdx.x * blockDim.x + threadIdx.x;
    if (i < E) {
        int d = ei[E + i];
        int pos = atomicAdd(&g_cur[d], 1);
        g_csr[pos] = ei[i];
    }
}

// ---------------- SMEM layouts for pq / node kernels -------------------------
#define SO_A0   0
#define SO_A1   32768
#define SO_B0   65536
#define SO_B1   81920
#define PQ_BE1  98304
#define PQ_MB   98816
#define PQ_SMEM 98848
#define NO_BH1  98304
#define NO_BH2  98816
#define NO_VB   99328
#define NO_MB   99840
#define NODE_SMEM 99872

// ---------------- PQ precompute: P = node@W_top + be1 ; Q = node@W_bot ------
__global__ __launch_bounds__(512, 1)
void pq_kernel(const float* __restrict__ be1, int N)
{
    extern __shared__ char sm[];
    const uint32_t sbase = smem_u32(sm);
    float* sBe1 = (float*)(sm + PQ_BE1);

    const int t    = threadIdx.x;
    const int wid  = t >> 5;
    const int lane = t & 31;
    const int n0   = blockIdx.x * ET2;

    const uint32_t mb0 = sbase + PQ_MB;
    const uint32_t mb1 = sbase + PQ_MB + 8;

    if (t == 0) { MB_INIT(mb0, 1); MB_INIT(mb1, 1); }
    if (t < 128) sBe1[t] = be1[t];
    __syncthreads();

    if (t == 0) {
        MB_EXPECT(mb0, BCH);
        BULK_G2S(sbase + SO_B0, (const void*)gB1[0], BCH, mb0);
        MB_EXPECT(mb1, BCH);
        BULK_G2S(sbase + SO_B1, (const void*)gB1[1], BCH, mb1);
    }

    const int grow  = t >> 1;
    const int ghalf = t & 1;
    const int grnode = n0 + grow;
    const bool gvalid = grnode < N;
    const int grclamp = gvalid ? grnode : 0;
    const uint32_t g_rowoff = (uint32_t)grow * 128;
    const int      g_rx     = grow & 7;
    const uint32_t g_nsz    = gvalid ? 16u : 0u;

    auto stageN = [&](int c, uint32_t abo) {
        const __half* rp = g_nodeh + (size_t)grclamp * 128 + c * 64 + ghalf * 32;
        #pragma unroll
        for (int u = 0; u < 4; ++u) {
            uint32_t dst = sbase + abo + g_rowoff + (uint32_t)(((ghalf * 4 + u) ^ g_rx) << 4);
            CPA16(dst, rp + u * 8, g_nsz);
        }
        CPA_COMMIT();
    };

    const int seg = lane >> 3;
    const int lnx = lane & 7;
    const int sA_r = seg & 1;
    const int sA_g = (seg >> 1) & 1;
    const int sB_r = (seg >> 1) & 1;
    const int sB_g = seg & 1;
    const uint32_t a_rowoff = (uint32_t)(wid * 16 + lnx + sA_r * 8) * 128;
    const uint32_t b_rowoff = (uint32_t)(lnx + sB_r * 8) * 128;

    auto doChunk = [&](uint32_t Ab, uint32_t Bb, float* cc) {
        #pragma unroll
        for (int ks = 0; ks < 4; ++ks) {
            uint32_t ag = (uint32_t)(((2 * ks) | sA_g) ^ lnx) << 4;
            uint32_t bg = (uint32_t)(((2 * ks) | sB_g) ^ lnx) << 4;
            uint32_t a0,a1,a2,a3;
            LDSM4(a0,a1,a2,a3, sbase + Ab + a_rowoff + ag);
            #pragma unroll
            for (int jb = 0; jb < 8; ++jb) {
                uint32_t baddr = sbase + Bb + b_rowoff + (uint32_t)(jb * 2048) + bg;
                uint32_t b0,b1,b2,b3;
                LDSM4(b0,b1,b2,b3, baddr);
                float* cp0 = cc + 8 * jb;
                float* cp1 = cc + 8 * jb + 4;
                MMA16816(cp0, a0,a1,a2,a3, b0,b1);
                MMA16816(cp1, a0,a1,a2,a3, b2,b3);
            }
        }
    };

    float cc[64];
    #pragma unroll
    for (int i = 0; i < 64; ++i) cc[i] = 0.0f;

    stageN(0, SO_A0);
    stageN(1, SO_A1);
    CPA_WAIT0();
    __syncthreads();

    // P pass
    mb_wait(mb0, 0);
    doChunk(SO_A0, SO_B0, cc);
    __syncthreads();
    if (t == 0) { MB_EXPECT(mb0, BCH); BULK_G2S(sbase + SO_B0, (const void*)gB1[2], BCH, mb0); }
    mb_wait(mb1, 0);
    doChunk(SO_A1, SO_B1, cc);
    __syncthreads();
    if (t == 0) { MB_EXPECT(mb1, BCH); BULK_G2S(sbase + SO_B1, (const void*)gB1[3], BCH, mb1); }

    const int r0 = wid * 16 + (lane >> 2);
    const int q  = lane & 3;
    const int row0 = n0 + r0;
    const int row1 = row0 + 8;

    #pragma unroll
    for (int f = 0; f < 16; ++f) {
        int col = 8 * f + 2 * q;
        float2 b = *(float2*)(sBe1 + col);
        if (row0 < N)
            *(uint32_t*)(g_Ph + (size_t)row0 * 128 + col) = packhf2(cc[4*f+0] + b.x, cc[4*f+1] + b.y);
        if (row1 < N)
            *(uint32_t*)(g_Ph + (size_t)row1 * 128 + col) = packhf2(cc[4*f+2] + b.x, cc[4*f+3] + b.y);
    }

    // Q pass
    #pragma unroll
    for (int i = 0; i < 64; ++i) cc[i] = 0.0f;
    mb_wait(mb0, 1);
    doChunk(SO_A0, SO_B0, cc);
    mb_wait(mb1, 1);
    doChunk(SO_A1, SO_B1, cc);

    #pragma unroll
    for (int f = 0; f < 16; ++f) {
        int col = 8 * f + 2 * q;
        if (row0 < N)
            *(uint32_t*)(g_Qh + (size_t)row0 * 128 + col) = packhf2(cc[4*f+0], cc[4*f+1]);
        if (row1 < N)
            *(uint32_t*)(g_Qh + (size_t)row1 * 128 + col) = packhf2(cc[4*f+2], cc[4*f+3]);
    }
}

// ---------------- aggregation: one warp per node (gather, no atomics) -------
__global__ __launch_bounds__(256)
void agg_kernel(const float* __restrict__ coord,
                const float* __restrict__ We1,
                int N)
{
    __shared__ __half sW256[128];
    __shared__ float  sWx2[128];
    const int t = threadIdx.x;
    if (t < 128) {
        sW256[t] = __float2half_rn(We1[(size_t)256 * 128 + t]);
        sWx2[t]  = g_wx2[t];
    }
    __syncthreads();

    const int node = (blockIdx.x * blockDim.x + t) >> 5;
    const int lane = t & 31;
    if (node >= N) return;

    const float cix = coord[(size_t)node * 3 + 0];
    const float ciy = coord[(size_t)node * 3 + 1];
    const float ciz = coord[(size_t)node * 3 + 2];
    const uint2 P2 = *(const uint2*)(g_Ph + (size_t)node * 128 + lane * 4);
    const uint2 W2 = *(const uint2*)(sW256 + lane * 4);
    const float4 wx = *(const float4*)(sWx2 + lane * 4);
    const float cxv = g_cx;

    float S0 = 0.f, S1 = 0.f, S2 = 0.f, S3 = 0.f;
    float ax = 0.f, ay = 0.f, az = 0.f;

    const int j0 = g_rowptr[node];
    const int j1 = g_rowptr[node + 1];

    for (int j = j0; j < j1; ++j) {
        int src = g_csr[j];                              // broadcast
        float dx = cix - coord[(size_t)src * 3 + 0];
        float dy = ciy - coord[(size_t)src * 3 + 1];
        float dz = ciz - coord[(size_t)src * 3 + 2];
        float sq = dx * dx + dy * dy + dz * dz;
        uint32_t sq2 = packhf2(sq, sq);

        uint2 Q2 = *(const uint2*)(g_Qh + (size_t)src * 128 + lane * 4);
        uint32_t h0 = h2_relu(h2_fma(sq2, W2.x, h2_add(P2.x, Q2.x)));
        uint32_t h1 = h2_relu(h2_fma(sq2, W2.y, h2_add(P2.y, Q2.y)));
        float2 f0 = h2_unpack(h0);
        float2 f1 = h2_unpack(h1);

        S0 += f0.x; S1 += f0.y; S2 += f1.x; S3 += f1.y;

        float wp = fmaf(f0.x, wx.x, fmaf(f0.y, wx.y, fmaf(f1.x, wx.z, f1.y * wx.w)));
        wp += __shfl_xor_sync(0xffffffffu, wp, 16);
        wp += __shfl_xor_sync(0xffffffffu, wp, 8);
        wp += __shfl_xor_sync(0xffffffffu, wp, 4);
        wp += __shfl_xor_sync(0xffffffffu, wp, 2);
        wp += __shfl_xor_sync(0xffffffffu, wp, 1);
        float w = wp + cxv;

        ax = fmaf(dx, w, ax);
        ay = fmaf(dy, w, ay);
        az = fmaf(dz, w, az);
    }

    *(float4*)(g_mi + (size_t)node * 128 + lane * 4) = make_float4(S0, S1, S2, S3);
    if (lane == 0)
        *(float4*)(g_dx4 + (size_t)node * 4) = make_float4(ax, ay, az, (float)(j1 - j0));
}

// ---------------- node kernel ------------------------------------------------
__global__ __launch_bounds__(512, 1)
void node_kernel(const float* __restrict__ bh1,
                 const float* __restrict__ bh2,
                 float* __restrict__ outH,
                 int N)
{
    extern __shared__ char sm[];
    const uint32_t sbase = smem_u32(sm);

    float* sBh1 = (float*)(sm + NO_BH1);
    float* sBh2 = (float*)(sm + NO_BH2);
    float* sVb  = (float*)(sm + NO_VB);

    const int t    = threadIdx.x;
    const int wid  = t >> 5;
    const int lane = t & 31;
    const int n0   = blockIdx.x * ET2;

    const uint32_t mb0 = sbase + NO_MB;
    const uint32_t mb1 = sbase + NO_MB + 8;

    if (t == 0) { MB_INIT(mb0, 1); MB_INIT(mb1, 1); }
    if (t < 128) {
        sBh1[t] = bh1[t];
        sBh2[t] = bh2[t];
        sVb[t]  = g_vb[t];
    }
    __syncthreads();

    if (t == 0) {
        MB_EXPECT(mb0, BCH);
        BULK_G2S(sbase + SO_B0, (const void*)gH1[0], BCH, mb0);
        MB_EXPECT(mb1, BCH);
        BULK_G2S(sbase + SO_B1, (const void*)gH1[1], BCH, mb1);
    }

    const int grow  = t >> 1;
    const int ghalf = t & 1;
    const int grnode = n0 + grow;
    const bool gvalid = grnode < N;
    const int grclamp = gvalid ? grnode : 0;
    const uint32_t g_rowoff = (uint32_t)grow * 128;
    const int      g_rx     = grow & 7;
    const uint32_t g_nsz    = gvalid ? 16u : 0u;

    auto stageN = [&](int c, uint32_t abo) {
        const __half* rp = g_nodeh + (size_t)grclamp * 128 + c * 64 + ghalf * 32;
        #pragma unroll
        for (int u = 0; u < 4; ++u) {
            uint32_t dst = sbase + abo + g_rowoff + (uint32_t)(((ghalf * 4 + u) ^ g_rx) << 4);
            CPA16(dst, rp + u * 8, g_nsz);
        }
        CPA_COMMIT();
    };
    auto stageM = [&](int c, uint32_t abo) {
        const float* rp = g_mi + (size_t)grclamp * 128 + (c - 2) * 64 + ghalf * 32;
        #pragma unroll
        for (int u = 0; u < 4; ++u) {
            uint4 H;
            if (gvalid) {
                float4 v0 = *(const float4*)(rp + u * 8);
                float4 v1 = *(const float4*)(rp + u * 8 + 4);
                H.x = packhf2(v0.x, v0.y);
                H.y = packhf2(v0.z, v0.w);
                H.z = packhf2(v1.x, v1.y);
                H.w = packhf2(v1.z, v1.w);
            } else {
                H = make_uint4(0u, 0u, 0u, 0u);
            }
            uint32_t off = g_rowoff + (uint32_t)(((ghalf * 4 + u) ^ g_rx) << 4);
            *(uint4*)(sm + abo + off) = H;
        }
    };

    const int seg = lane >> 3;
    const int lnx = lane & 7;
    const int sA_r = seg & 1;
    const int sA_g = (seg >> 1) & 1;
    const int sB_r = (seg >> 1) & 1;
    const int sB_g = seg & 1;
    const uint32_t a_rowoff = (uint32_t)(wid * 16 + lnx + sA_r * 8) * 128;
    const uint32_t b_rowoff = (uint32_t)(lnx + sB_r * 8) * 128;

    auto doChunk = [&](uint32_t Ab, uint32_t Bb, float* cc) {
        #pragma unroll
        for (int ks = 0; ks < 4; ++ks) {
            uint32_t ag = (uint32_t)(((2 * ks) | sA_g) ^ lnx) << 4;
            uint32_t bg = (uint32_t)(((2 * ks) | sB_g) ^ lnx) << 4;
            uint32_t a0,a1,a2,a3;
            LDSM4(a0,a1,a2,a3, sbase + Ab + a_rowoff + ag);
            #pragma unroll
            for (int jb = 0; jb < 8; ++jb) {
                uint32_t baddr = sbase + Bb + b_rowoff + (uint32_t)(jb * 2048) + bg;
                uint32_t b0,b1,b2,b3;
                LDSM4(b0,b1,b2,b3, baddr);
                float* cp0 = cc + 8 * jb;
                float* cp1 = cc + 8 * jb + 4;
                MMA16816(cp0, a0,a1,a2,a3, b0,b1);
                MMA16816(cp1, a0,a1,a2,a3, b2,b3);
            }
        }
    };

    float c1[64];
    #pragma unroll
    for (int i = 0; i < 64; ++i) c1[i] = 0.0f;

    stageN(0, SO_A0);
    CPA_WAIT0();
    __syncthreads();

    uint32_t ph0 = 0, ph1 = 0;

    #pragma unroll 1
    for (int c = 0; c < 4; ++c) {
        if (c & 1) { mb_wait(mb1, ph1); ph1 ^= 1; }
        else       { mb_wait(mb0, ph0); ph0 ^= 1; }

        if (c == 0)      stageN(1, SO_A1);
        else if (c == 1) stageM(2, SO_A0);
        else if (c == 2) stageM(3, SO_A1);

        doChunk((c & 1) ? SO_A1 : SO_A0, (c & 1) ? SO_B1 : SO_B0, c1);
        CPA_WAIT0();
        __syncthreads();

        if (t == 0) {
            const void* nsrc = (c == 0) ? (const void*)gW2h[0]
                             : (c == 1) ? (const void*)gW2h[1]
                             : (c == 2) ? (const void*)gH2[0]
                                        : (const void*)gH2[1];
            uint32_t dst = (c & 1) ? (sbase + SO_B1) : (sbase + SO_B0);
            uint32_t mb  = (c & 1) ? mb1 : mb0;
            MB_EXPECT(mb, BCH);
            BULK_G2S(dst, nsrc, BCH, mb);
        }
    }

    const int r0 = wid * 16 + (lane >> 2);
    const int q  = lane & 3;
    const int row0 = n0 + r0;
    const int row1 = row0 + 8;
    const float deg0 = (row0 < N) ? g_dx4[(size_t)row0 * 4 + 3] : 0.0f;
    const float deg1 = (row1 < N) ? g_dx4[(size_t)row1 * 4 + 3] : 0.0f;

    const uint32_t hrow0 = (uint32_t)r0 * 128;
    const int      hrx   = r0 & 7;
    #pragma unroll
    for (int f = 0; f < 16; ++f) {
        int col = 8 * f + 2 * q;
        float2 b  = *(float2*)(sBh1 + col);
        float2 vb = *(float2*)(sVb + col);
        float v0 = fmaxf(c1[4*f+0] + b.x + deg0 * vb.x, 0.0f);
        float v1 = fmaxf(c1[4*f+1] + b.y + deg0 * vb.y, 0.0f);
        float v2 = fmaxf(c1[4*f+2] + b.x + deg1 * vb.x, 0.0f);
        float v3 = fmaxf(c1[4*f+3] + b.y + deg1 * vb.y, 0.0f);

        uint32_t h01 = packhf2(v0, v1);
        uint32_t h23 = packhf2(v2, v3);

        uint32_t abuf = (col >> 6) ? SO_A1 : SO_A0;
        int kc = col & 63;
        uint32_t off = hrow0 + (uint32_t)((((kc >> 3) ^ hrx) << 4) | ((kc & 7) << 1));
        *(uint32_t*)(sm + abuf + off)        = h01;
        *(uint32_t*)(sm + abuf + off + 1024) = h23;
    }
    __syncwarp();

    float c2[64];
    #pragma unroll
    for (int i = 0; i < 64; ++i) c2[i] = 0.0f;

    mb_wait(mb0, ph0); ph0 ^= 1;
    doChunk(SO_A0, SO_B0, c2);
    mb_wait(mb1, ph1); ph1 ^= 1;
    doChunk(SO_A1, SO_B1, c2);

    #pragma unroll
    for (int f = 0; f < 16; ++f) {
        int col = 8 * f + 2 * q;
        float2 b = *(float2*)(sBh2 + col);
        if (row0 < N) {
            float2 v; v.x = c2[4*f+0] + b.x; v.y = c2[4*f+1] + b.y;
            *(float2*)(outH + (size_t)row0 * Fdim + col) = v;
        }
        if (row1 < N) {
            float2 v; v.x = c2[4*f+2] + b.x; v.y = c2[4*f+3] + b.y;
            *(float2*)(outH + (size_t)row1 * Fdim + col) = v;
        }
    }
}

// ---------------- coordinate update -----------------------------------------
__global__ void x_kernel(const float* __restrict__ coord,
                         float* __restrict__ outX,
                         int n3, float C)
{
    int i = blockIdx.x * blockDim.x + threadIdx.x;
    if (i < n3) {
        int n = i / 3, d = i - n * 3;
        outX[i] = coord[i] + g_dx4[(size_t)n * 4 + d] * C;
    }
}

// ---------------- launch -----------------------------------------------------
extern "C" void kernel_launch(void* const* d_in, const int* in_sizes, int n_in,
                              void* d_out, int out_size)
{
    const float* node  = (const float*)d_in[0];
    const float* coord = (const float*)d_in[1];
    const int*   ei    = (const int*)d_in[2];
    const float* We1   = (const float*)d_in[3];
    const float* be1   = (const float*)d_in[4];
    const float* We2   = (const float*)d_in[5];
    const float* be2   = (const float*)d_in[6];
    const float* Wx    = (const float*)d_in[7];
    const float* bx    = (const float*)d_in[8];
    const float* Wh1   = (const float*)d_in[9];
    const float* bh1   = (const float*)d_in[10];
    const float* Wh2   = (const float*)d_in[11];
    const float* bh2   = (const float*)d_in[12];

    const int N = in_sizes[0] / Fdim;
    const int E = in_sizes[2] / 2;

    float* outH = (float*)d_out;
    float* outX = outH + (size_t)N * Fdim;

    cudaFuncSetAttribute(pq_kernel,   cudaFuncAttributeMaxDynamicSharedMemorySize, PQ_SMEM);
    cudaFuncSetAttribute(node_kernel, cudaFuncAttributeMaxDynamicSharedMemorySize, NODE_SMEM);

    prep_kernel<<<(65536 + 255) / 256, 256>>>(We1, Wh1, Wh2);
    prep2_kernel<<<(16641 + 255) / 256, 256>>>(We2, Wh1, Wx, be2, bx);
    {
        int n_mi = N * 128;
        zero_kernel<<<(n_mi + 255) / 256, 256>>>(node, n_mi, N);
    }
    hist_kernel<<<(E + 255) / 256, 256>>>(ei, E);
    {
        int grid = (N + ET2 - 1) / ET2;
        pq_kernel<<<grid, 512, PQ_SMEM>>>(be1, N);
    }
    scan_kernel<<<1, 1024>>>(N);
    place_kernel<<<(E + 255) / 256, 256>>>(ei, E);
    {
        int grid = (N * 32 + 255) / 256;
        agg_kernel<<<grid, 256>>>(coord, We1, N);
    }
    {
        int grid = (N + ET2 - 1) / ET2;
        node_kernel<<<grid, 512, NODE_SMEM>>>(bh1, bh2, outH, N);
    }
    {
        int n3 = N * 3;
        float C = 1.0f / (float)(N - 1);
        x_kernel<<<(n3 + 255) / 256, 256>>>(coord, outX, n3, C);
    }
}

// round 14
// speedup vs baseline: 1.9326x; 1.0426x over previous
#include <cuda_runtime.h>
#include <cuda_fp16.h>
#include <cstdint>

#define Fdim 128
#define ET2  256              // rows per CTA tile for pq/node kernels
#define MAXN 50000
#define MAXE 800000

// ---------------- scratch (static device arrays; allocation-free) ----------
__device__ float g_mi[(size_t)MAXN * 128];        // S = sum of hidden per node (fp32)
__device__ float g_dx4[(size_t)MAXN * 4];         // xyz delta + .w = degree
__device__ __align__(16) __half g_nodeh[(size_t)MAXN * 128];   // fp16 node table
__device__ __align__(16) __half g_Ph[(size_t)MAXN * 128];      // fp16: node@We1_top + be1
__device__ __align__(16) __half g_Qh[(size_t)MAXN * 128];      // fp16: node@We1_bot
// CSR (dst -> incoming edges)
__device__ int g_cnt[MAXN];
__device__ int g_cur[MAXN];
__device__ int g_rowptr[MAXN + 1];
__device__ int g_csr[MAXE];
// swizzled fp16 weight chunk images: rows=n(128), kc(64)
__device__ __align__(16) __half gB1[4][8192];     // We1 (k chunks 0..3)
__device__ __align__(16) __half gH1[2][8192];     // Wh1_top (k chunks 0..1)
__device__ __align__(16) __half gH2[2][8192];     // Wh2
__device__ __align__(16) __half gW2h[2][8192];    // We2 @ Wh1_bot
__device__ float g_wx2[128];                      // We2 @ Wx
__device__ float g_vb[128];                       // be2 @ Wh1_bot
__device__ float g_cx;                            // be2 . Wx + bx

#define BCH 16384            /* bytes per B chunk */

// ---------------- PTX helpers ----------------------------------------------
__device__ __forceinline__ uint32_t smem_u32(const void* p) {
    uint32_t a;
    asm("{ .reg .u64 t; cvta.to.shared.u64 t, %1; cvt.u32.u64 %0, t; }" : "=r"(a) : "l"(p));
    return a;
}

#define LDSM4(r0, r1, r2, r3, addr) \
    asm volatile("ldmatrix.sync.aligned.m8n8.x4.shared.b16 {%0,%1,%2,%3}, [%4];" \
                 : "=r"(r0), "=r"(r1), "=r"(r2), "=r"(r3) : "r"(addr))

#define MMA16816(cp, a0, a1, a2, a3, b0, b1) \
    asm volatile("mma.sync.aligned.m16n8k16.row.col.f32.f16.f16.f32 " \
                 "{%0,%1,%2,%3},{%4,%5,%6,%7},{%8,%9},{%0,%1,%2,%3};" \
                 : "+f"((cp)[0]), "+f"((cp)[1]), "+f"((cp)[2]), "+f"((cp)[3]) \
                 : "r"(a0), "r"(a1), "r"(a2), "r"(a3), "r"(b0), "r"(b1))

#define MB_INIT(mb, c) asm volatile("mbarrier.init.shared.b64 [%0], %1;" :: "r"(mb), "r"(c) : "memory")
#define MB_EXPECT(mb, b) asm volatile("mbarrier.arrive.expect_tx.shared.b64 _, [%0], %1;" :: "r"(mb), "r"(b) : "memory")
#define BULK_G2S(dst, src, bytes, mb) \
    asm volatile("cp.async.bulk.shared::cluster.global.mbarrier::complete_tx::bytes [%0], [%1], %2, [%3];" \
                 :: "r"(dst), "l"(src), "r"(bytes), "r"(mb) : "memory")

#define CPA16(dst, src, n) \
    asm volatile("cp.async.cg.shared.global [%0], [%1], 16, %2;" :: "r"(dst), "l"(src), "r"(n) : "memory")
#define CPA_COMMIT() asm volatile("cp.async.commit_group;" ::: "memory")
#define CPA_WAIT0()  asm volatile("cp.async.wait_group 0;" ::: "memory")

__device__ __forceinline__ void mb_wait(uint32_t mb, uint32_t parity) {
    uint32_t done;
    asm volatile("{ .reg .pred p; mbarrier.try_wait.parity.acquire.cta.shared::cta.b64 p, [%1], %2; selp.b32 %0, 1, 0, p; }"
                 : "=r"(done) : "r"(mb), "r"(parity) : "memory");
    if (!done) {
        asm volatile("{ .reg .pred P1;\nW%=:\n mbarrier.try_wait.parity.acquire.cta.shared::cta.b64 P1, [%0], %1, 0x989680;\n @P1 bra.uni D%=;\n bra.uni W%=;\nD%=:\n}"
                     :: "r"(mb), "r"(parity) : "memory");
    }
}

__device__ __forceinline__ uint32_t packhf2(float a, float b) {
    uint32_t r;
    asm("cvt.rn.f16x2.f32 %0, %1, %2;" : "=r"(r) : "f"(b), "f"(a));
    return r;
}

// packed half2 helpers on raw uint32 bit patterns
__device__ __forceinline__ uint32_t h2_add(uint32_t a, uint32_t b) {
    uint32_t r;
    asm("add.f16x2 %0, %1, %2;" : "=r"(r) : "r"(a), "r"(b));
    return r;
}
__device__ __forceinline__ uint32_t h2_fma(uint32_t a, uint32_t b, uint32_t c) {
    uint32_t r;
    asm("fma.rn.f16x2 %0, %1, %2, %3;" : "=r"(r) : "r"(a), "r"(b), "r"(c));
    return r;
}
__device__ __forceinline__ uint32_t h2_relu(uint32_t a) {
    uint32_t r;
    asm("max.f16x2 %0, %1, %2;" : "=r"(r) : "r"(a), "r"(0u));
    return r;
}
__device__ __forceinline__ float2 h2_unpack(uint32_t h) {
    float2 r;
    asm("{ .reg .b16 lo, hi; mov.b32 {lo, hi}, %2; cvt.f32.f16 %0, lo; cvt.f32.f16 %1, hi; }"
        : "=f"(r.x), "=f"(r.y) : "r"(h));
    return r;
}

// swizzled element offset within a [row][kc] tile, 64 fp16 per row (128 B)
__host__ __device__ __forceinline__ int swoff(int n, int kc) {
    return n * 64 + ((((kc >> 3) ^ (n & 7)) << 3) | (kc & 7));
}

// ---------------- prep: swizzled fp16 weight chunk images -------------------
__global__ void prep_kernel(const float* __restrict__ We1,
                            const float* __restrict__ Wh1,
                            const float* __restrict__ Wh2)
{
    int id = blockIdx.x * blockDim.x + threadIdx.x;
    if (id < 32768) {                               // We1 4 chunks
        int c = id >> 13, rem = id & 8191, n = rem >> 6, kc = rem & 63;
        gB1[c][swoff(n, kc)] = __float2half_rn(We1[(size_t)(c * 64 + kc) * 128 + n]);
    } else if (id < 49152) {                        // Wh1_top 2 chunks
        int id2 = id - 32768;
        int c = id2 >> 13, rem = id2 & 8191, n = rem >> 6, kc = rem & 63;
        gH1[c][swoff(n, kc)] = __float2half_rn(Wh1[(size_t)(c * 64 + kc) * 128 + n]);
    } else if (id < 65536) {                        // Wh2 2 chunks
        int id2 = id - 49152;
        int c = id2 >> 13, rem = id2 & 8191, n = rem >> 6, kc = rem & 63;
        gH2[c][swoff(n, kc)] = __float2half_rn(Wh2[(size_t)(c * 64 + kc) * 128 + n]);
    }
}

// ---------------- prep2: folded-weight products -------------------------------
__global__ void prep2_kernel(const float* __restrict__ We2,
                             const float* __restrict__ Wh1,
                             const float* __restrict__ Wx,
                             const float* __restrict__ be2,
                             const float* __restrict__ bxp)
{
    int id = blockIdx.x * blockDim.x + threadIdx.x;
    if (id < 16384) {
        int c  = id >> 13;
        int rem = id & 8191;
        int kc = rem >> 7;
        int n  = rem & 127;
        int k  = c * 64 + kc;
        float acc = 0.0f;
        #pragma unroll 4
        for (int j = 0; j < 128; ++j)
            acc = fmaf(We2[(size_t)k * 128 + j], Wh1[(size_t)(128 + j) * 128 + n], acc);
        gW2h[c][swoff(n, kc)] = __float2half_rn(acc);
    } else if (id < 16512) {
        int k = id - 16384;
        float acc = 0.0f;
        for (int j = 0; j < 128; ++j)
            acc = fmaf(We2[(size_t)k * 128 + j], Wx[j], acc);
        g_wx2[k] = acc;
    } else if (id < 16640) {
        int n = id - 16512;
        float acc = 0.0f;
        for (int j = 0; j < 128; ++j)
            acc = fmaf(be2[j], Wh1[(size_t)(128 + j) * 128 + n], acc);
        g_vb[n] = acc;
    } else if (id == 16640) {
        float acc = bxp[0];
        for (int j = 0; j < 128; ++j)
            acc = fmaf(be2[j], Wx[j], acc);
        g_cx = acc;
    }
}

// ---------------- zero: convert node table + clear CSR counters -------------
__global__ void zero_kernel(const float* __restrict__ node, int n_mi, int N)
{
    int i = blockIdx.x * blockDim.x + threadIdx.x;
    if (i < n_mi) g_nodeh[i] = __float2half_rn(node[i]);
    if (i < N) g_cnt[i] = 0;
}

// ---------------- CSR build ---------------------------------------------------
__global__ void hist_kernel(const int* __restrict__ ei, int E)
{
    int i = blockIdx.x * blockDim.x + threadIdx.x;
    if (i < E) atomicAdd(&g_cnt[ei[E + i]], 1);
}

__global__ void scan_kernel(int N)
{
    __shared__ int ssum[1024];
    const int t = threadIdx.x;
    const int CH = (N + 1023) / 1024;
    const int b = t * CH;
    const int e = min(b + CH, N);
    int s = 0;
    for (int i = b; i < e; ++i) s += g_cnt[i];
    ssum[t] = s;
    __syncthreads();
    for (int off = 1; off < 1024; off <<= 1) {
        int v = (t >= off) ? ssum[t - off] : 0;
        __syncthreads();
        ssum[t] += v;
        __syncthreads();
    }
    int base = ssum[t] - s;       // exclusive prefix
    for (int i = b; i < e; ++i) {
        int c = g_cnt[i];
        g_rowptr[i] = base;
        g_cur[i]    = base;
        base += c;
    }
    if (t == 1023) g_rowptr[N] = base;
}

__global__ void place_kernel(const int* __restrict__ ei, int E)
{
    int i = blockIdx.x * blockDim.x + threadIdx.x;
    if (i < E) {
        int d = ei[E + i];
        int pos = atomicAdd(&g_cur[d], 1);
        g_csr[pos] = ei[i];
    }
}

// ---------------- SMEM layouts for pq / node kernels -------------------------
#define SO_A0   0
#define SO_A1   32768
#define SO_B0   65536
#define SO_B1   81920
#define PQ_BE1  98304
#define PQ_MB   98816
#define PQ_SMEM 98848
#define NO_BH1  98304
#define NO_BH2  98816
#define NO_VB   99328
#define NO_MB   99840
#define NODE_SMEM 99872

// ---------------- PQ precompute: P = node@W_top + be1 ; Q = node@W_bot ------
__global__ __launch_bounds__(512, 1)
void pq_kernel(const float* __restrict__ be1, int N)
{
    extern __shared__ char sm[];
    const uint32_t sbase = smem_u32(sm);
    float* sBe1 = (float*)(sm + PQ_BE1);

    const int t    = threadIdx.x;
    const int wid  = t >> 5;
    const int lane = t & 31;
    const int n0   = blockIdx.x * ET2;

    const uint32_t mb0 = sbase + PQ_MB;
    const uint32_t mb1 = sbase + PQ_MB + 8;

    if (t == 0) { MB_INIT(mb0, 1); MB_INIT(mb1, 1); }
    if (t < 128) sBe1[t] = be1[t];
    __syncthreads();

    if (t == 0) {
        MB_EXPECT(mb0, BCH);
        BULK_G2S(sbase + SO_B0, (const void*)gB1[0], BCH, mb0);
        MB_EXPECT(mb1, BCH);
        BULK_G2S(sbase + SO_B1, (const void*)gB1[1], BCH, mb1);
    }

    const int grow  = t >> 1;
    const int ghalf = t & 1;
    const int grnode = n0 + grow;
    const bool gvalid = grnode < N;
    const int grclamp = gvalid ? grnode : 0;
    const uint32_t g_rowoff = (uint32_t)grow * 128;
    const int      g_rx     = grow & 7;
    const uint32_t g_nsz    = gvalid ? 16u : 0u;

    auto stageN = [&](int c, uint32_t abo) {
        const __half* rp = g_nodeh + (size_t)grclamp * 128 + c * 64 + ghalf * 32;
        #pragma unroll
        for (int u = 0; u < 4; ++u) {
            uint32_t dst = sbase + abo + g_rowoff + (uint32_t)(((ghalf * 4 + u) ^ g_rx) << 4);
            CPA16(dst, rp + u * 8, g_nsz);
        }
        CPA_COMMIT();
    };

    const int seg = lane >> 3;
    const int lnx = lane & 7;
    const int sA_r = seg & 1;
    const int sA_g = (seg >> 1) & 1;
    const int sB_r = (seg >> 1) & 1;
    const int sB_g = seg & 1;
    const uint32_t a_rowoff = (uint32_t)(wid * 16 + lnx + sA_r * 8) * 128;
    const uint32_t b_rowoff = (uint32_t)(lnx + sB_r * 8) * 128;

    auto doChunk = [&](uint32_t Ab, uint32_t Bb, float* cc) {
        #pragma unroll
        for (int ks = 0; ks < 4; ++ks) {
            uint32_t ag = (uint32_t)(((2 * ks) | sA_g) ^ lnx) << 4;
            uint32_t bg = (uint32_t)(((2 * ks) | sB_g) ^ lnx) << 4;
            uint32_t a0,a1,a2,a3;
            LDSM4(a0,a1,a2,a3, sbase + Ab + a_rowoff + ag);
            #pragma unroll
            for (int jb = 0; jb < 8; ++jb) {
                uint32_t baddr = sbase + Bb + b_rowoff + (uint32_t)(jb * 2048) + bg;
                uint32_t b0,b1,b2,b3;
                LDSM4(b0,b1,b2,b3, baddr);
                float* cp0 = cc + 8 * jb;
                float* cp1 = cc + 8 * jb + 4;
                MMA16816(cp0, a0,a1,a2,a3, b0,b1);
                MMA16816(cp1, a0,a1,a2,a3, b2,b3);
            }
        }
    };

    float cc[64];
    #pragma unroll
    for (int i = 0; i < 64; ++i) cc[i] = 0.0f;

    stageN(0, SO_A0);
    stageN(1, SO_A1);
    CPA_WAIT0();
    __syncthreads();

    // P pass
    mb_wait(mb0, 0);
    doChunk(SO_A0, SO_B0, cc);
    __syncthreads();
    if (t == 0) { MB_EXPECT(mb0, BCH); BULK_G2S(sbase + SO_B0, (const void*)gB1[2], BCH, mb0); }
    mb_wait(mb1, 0);
    doChunk(SO_A1, SO_B1, cc);
    __syncthreads();
    if (t == 0) { MB_EXPECT(mb1, BCH); BULK_G2S(sbase + SO_B1, (const void*)gB1[3], BCH, mb1); }

    const int r0 = wid * 16 + (lane >> 2);
    const int q  = lane & 3;
    const int row0 = n0 + r0;
    const int row1 = row0 + 8;

    #pragma unroll
    for (int f = 0; f < 16; ++f) {
        int col = 8 * f + 2 * q;
        float2 b = *(float2*)(sBe1 + col);
        if (row0 < N)
            *(uint32_t*)(g_Ph + (size_t)row0 * 128 + col) = packhf2(cc[4*f+0] + b.x, cc[4*f+1] + b.y);
        if (row1 < N)
            *(uint32_t*)(g_Ph + (size_t)row1 * 128 + col) = packhf2(cc[4*f+2] + b.x, cc[4*f+3] + b.y);
    }

    // Q pass
    #pragma unroll
    for (int i = 0; i < 64; ++i) cc[i] = 0.0f;
    mb_wait(mb0, 1);
    doChunk(SO_A0, SO_B0, cc);
    mb_wait(mb1, 1);
    doChunk(SO_A1, SO_B1, cc);

    #pragma unroll
    for (int f = 0; f < 16; ++f) {
        int col = 8 * f + 2 * q;
        if (row0 < N)
            *(uint32_t*)(g_Qh + (size_t)row0 * 128 + col) = packhf2(cc[4*f+0], cc[4*f+1]);
        if (row1 < N)
            *(uint32_t*)(g_Qh + (size_t)row1 * 128 + col) = packhf2(cc[4*f+2], cc[4*f+3]);
    }
}

// ---------------- aggregation: one warp per node, no per-edge reduction -----
// Lane-partial trick: w_j = sum_l wp_{l,j} + cx, so
//   sum_j d_j w_j = sum_l (sum_j d_j wp_{l,j}) + cx * (sum_j d_j)
// Each lane accumulates ax_l += dx*wp_l; one warp reduction at the end.
__global__ __launch_bounds__(256)
void agg_kernel(const float* __restrict__ coord,
                const float* __restrict__ We1,
                int N)
{
    __shared__ __half sW256[128];
    __shared__ float  sWx2[128];
    const int t = threadIdx.x;
    if (t < 128) {
        sW256[t] = __float2half_rn(We1[(size_t)256 * 128 + t]);
        sWx2[t]  = g_wx2[t];
    }
    __syncthreads();

    const int node = (blockIdx.x * blockDim.x + t) >> 5;
    const int lane = t & 31;
    if (node >= N) return;

    const float cix = coord[(size_t)node * 3 + 0];
    const float ciy = coord[(size_t)node * 3 + 1];
    const float ciz = coord[(size_t)node * 3 + 2];
    const uint2 P2 = *(const uint2*)(g_Ph + (size_t)node * 128 + lane * 4);
    const uint2 W2 = *(const uint2*)(sW256 + lane * 4);
    const float4 wx = *(const float4*)(sWx2 + lane * 4);

    float S0 = 0.f, S1 = 0.f, S2 = 0.f, S3 = 0.f;
    float axl = 0.f, ayl = 0.f, azl = 0.f;          // lane-partial w contributions
    float sdx = 0.f, sdy = 0.f, sdz = 0.f;          // plain dist sums (same all lanes)

    const int j0 = g_rowptr[node];
    const int j1 = g_rowptr[node + 1];

    for (int j = j0; j < j1; ++j) {
        int src = g_csr[j];                              // broadcast
        float dx = cix - coord[(size_t)src * 3 + 0];
        float dy = ciy - coord[(size_t)src * 3 + 1];
        float dz = ciz - coord[(size_t)src * 3 + 2];
        float sq = dx * dx + dy * dy + dz * dz;
        uint32_t sq2 = packhf2(sq, sq);

        uint2 Q2 = *(const uint2*)(g_Qh + (size_t)src * 128 + lane * 4);
        uint32_t h0 = h2_relu(h2_fma(sq2, W2.x, h2_add(P2.x, Q2.x)));
        uint32_t h1 = h2_relu(h2_fma(sq2, W2.y, h2_add(P2.y, Q2.y)));
        float2 f0 = h2_unpack(h0);
        float2 f1 = h2_unpack(h1);

        S0 += f0.x; S1 += f0.y; S2 += f1.x; S3 += f1.y;

        float wp = fmaf(f0.x, wx.x, fmaf(f0.y, wx.y, fmaf(f1.x, wx.z, f1.y * wx.w)));
        axl = fmaf(dx, wp, axl);
        ayl = fmaf(dy, wp, ayl);
        azl = fmaf(dz, wp, azl);
        sdx += dx; sdy += dy; sdz += dz;
    }

    *(float4*)(g_mi + (size_t)node * 128 + lane * 4) = make_float4(S0, S1, S2, S3);

    // one warp reduction per node
    #pragma unroll
    for (int off = 16; off > 0; off >>= 1) {
        axl += __shfl_xor_sync(0xffffffffu, axl, off);
        ayl += __shfl_xor_sync(0xffffffffu, ayl, off);
        azl += __shfl_xor_sync(0xffffffffu, azl, off);
    }
    if (lane == 0) {
        const float cxv = g_cx;
        *(float4*)(g_dx4 + (size_t)node * 4) =
            make_float4(fmaf(cxv, sdx, axl), fmaf(cxv, sdy, ayl), fmaf(cxv, sdz, azl),
                        (float)(j1 - j0));
    }
}

// ---------------- node kernel ------------------------------------------------
__global__ __launch_bounds__(512, 1)
void node_kernel(const float* __restrict__ bh1,
                 const float* __restrict__ bh2,
                 float* __restrict__ outH,
                 int N)
{
    extern __shared__ char sm[];
    const uint32_t sbase = smem_u32(sm);

    float* sBh1 = (float*)(sm + NO_BH1);
    float* sBh2 = (float*)(sm + NO_BH2);
    float* sVb  = (float*)(sm + NO_VB);

    const int t    = threadIdx.x;
    const int wid  = t >> 5;
    const int lane = t & 31;
    const int n0   = blockIdx.x * ET2;

    const uint32_t mb0 = sbase + NO_MB;
    const uint32_t mb1 = sbase + NO_MB + 8;

    if (t == 0) { MB_INIT(mb0, 1); MB_INIT(mb1, 1); }
    if (t < 128) {
        sBh1[t] = bh1[t];
        sBh2[t] = bh2[t];
        sVb[t]  = g_vb[t];
    }
    __syncthreads();

    if (t == 0) {
        MB_EXPECT(mb0, BCH);
        BULK_G2S(sbase + SO_B0, (const void*)gH1[0], BCH, mb0);
        MB_EXPECT(mb1, BCH);
        BULK_G2S(sbase + SO_B1, (const void*)gH1[1], BCH, mb1);
    }

    const int grow  = t >> 1;
    const int ghalf = t & 1;
    const int grnode = n0 + grow;
    const bool gvalid = grnode < N;
    const int grclamp = gvalid ? grnode : 0;
    const uint32_t g_rowoff = (uint32_t)grow * 128;
    const int      g_rx     = grow & 7;
    const uint32_t g_nsz    = gvalid ? 16u : 0u;

    auto stageN = [&](int c, uint32_t abo) {
        const __half* rp = g_nodeh + (size_t)grclamp * 128 + c * 64 + ghalf * 32;
        #pragma unroll
        for (int u = 0; u < 4; ++u) {
            uint32_t dst = sbase + abo + g_rowoff + (uint32_t)(((ghalf * 4 + u) ^ g_rx) << 4);
            CPA16(dst, rp + u * 8, g_nsz);
        }
        CPA_COMMIT();
    };
    auto stageM = [&](int c, uint32_t abo) {
        const float* rp = g_mi + (size_t)grclamp * 128 + (c - 2) * 64 + ghalf * 32;
        #pragma unroll
        for (int u = 0; u < 4; ++u) {
            uint4 H;
            if (gvalid) {
                float4 v0 = *(const float4*)(rp + u * 8);
                float4 v1 = *(const float4*)(rp + u * 8 + 4);
                H.x = packhf2(v0.x, v0.y);
                H.y = packhf2(v0.z, v0.w);
                H.z = packhf2(v1.x, v1.y);
                H.w = packhf2(v1.z, v1.w);
            } else {
                H = make_uint4(0u, 0u, 0u, 0u);
            }
            uint32_t off = g_rowoff + (uint32_t)(((ghalf * 4 + u) ^ g_rx) << 4);
            *(uint4*)(sm + abo + off) = H;
        }
    };

    const int seg = lane >> 3;
    const int lnx = lane & 7;
    const int sA_r = seg & 1;
    const int sA_g = (seg >> 1) & 1;
    const int sB_r = (seg >> 1) & 1;
    const int sB_g = seg & 1;
    const uint32_t a_rowoff = (uint32_t)(wid * 16 + lnx + sA_r * 8) * 128;
    const uint32_t b_rowoff = (uint32_t)(lnx + sB_r * 8) * 128;

    auto doChunk = [&](uint32_t Ab, uint32_t Bb, float* cc) {
        #pragma unroll
        for (int ks = 0; ks < 4; ++ks) {
            uint32_t ag = (uint32_t)(((2 * ks) | sA_g) ^ lnx) << 4;
            uint32_t bg = (uint32_t)(((2 * ks) | sB_g) ^ lnx) << 4;
            uint32_t a0,a1,a2,a3;
            LDSM4(a0,a1,a2,a3, sbase + Ab + a_rowoff + ag);
            #pragma unroll
            for (int jb = 0; jb < 8; ++jb) {
                uint32_t baddr = sbase + Bb + b_rowoff + (uint32_t)(jb * 2048) + bg;
                uint32_t b0,b1,b2,b3;
                LDSM4(b0,b1,b2,b3, baddr);
                float* cp0 = cc + 8 * jb;
                float* cp1 = cc + 8 * jb + 4;
                MMA16816(cp0, a0,a1,a2,a3, b0,b1);
                MMA16816(cp1, a0,a1,a2,a3, b2,b3);
            }
        }
    };

    float c1[64];
    #pragma unroll
    for (int i = 0; i < 64; ++i) c1[i] = 0.0f;

    stageN(0, SO_A0);
    CPA_WAIT0();
    __syncthreads();

    uint32_t ph0 = 0, ph1 = 0;

    #pragma unroll 1
    for (int c = 0; c < 4; ++c) {
        if (c & 1) { mb_wait(mb1, ph1); ph1 ^= 1; }
        else       { mb_wait(mb0, ph0); ph0 ^= 1; }

        if (c == 0)      stageN(1, SO_A1);
        else if (c == 1) stageM(2, SO_A0);
        else if (c == 2) stageM(3, SO_A1);

        doChunk((c & 1) ? SO_A1 : SO_A0, (c & 1) ? SO_B1 : SO_B0, c1);
        CPA_WAIT0();
        __syncthreads();

        if (t == 0) {
            const void* nsrc = (c == 0) ? (const void*)gW2h[0]
                             : (c == 1) ? (const void*)gW2h[1]
                             : (c == 2) ? (const void*)gH2[0]
                                        : (const void*)gH2[1];
            uint32_t dst = (c & 1) ? (sbase + SO_B1) : (sbase + SO_B0);
            uint32_t mb  = (c & 1) ? mb1 : mb0;
            MB_EXPECT(mb, BCH);
            BULK_G2S(dst, nsrc, BCH, mb);
        }
    }

    const int r0 = wid * 16 + (lane >> 2);
    const int q  = lane & 3;
    const int row0 = n0 + r0;
    const int row1 = row0 + 8;
    const float deg0 = (row0 < N) ? g_dx4[(size_t)row0 * 4 + 3] : 0.0f;
    const float deg1 = (row1 < N) ? g_dx4[(size_t)row1 * 4 + 3] : 0.0f;

    const uint32_t hrow0 = (uint32_t)r0 * 128;
    const int      hrx   = r0 & 7;
    #pragma unroll
    for (int f = 0; f < 16; ++f) {
        int col = 8 * f + 2 * q;
        float2 b  = *(float2*)(sBh1 + col);
        float2 vb = *(float2*)(sVb + col);
        float v0 = fmaxf(c1[4*f+0] + b.x + deg0 * vb.x, 0.0f);
        float v1 = fmaxf(c1[4*f+1] + b.y + deg0 * vb.y, 0.0f);
        float v2 = fmaxf(c1[4*f+2] + b.x + deg1 * vb.x, 0.0f);
        float v3 = fmaxf(c1[4*f+3] + b.y + deg1 * vb.y, 0.0f);

        uint32_t h01 = packhf2(v0, v1);
        uint32_t h23 = packhf2(v2, v3);

        uint32_t abuf = (col >> 6) ? SO_A1 : SO_A0;
        int kc = col & 63;
        uint32_t off = hrow0 + (uint32_t)((((kc >> 3) ^ hrx) << 4) | ((kc & 7) << 1));
        *(uint32_t*)(sm + abuf + off)        = h01;
        *(uint32_t*)(sm + abuf + off + 1024) = h23;
    }
    __syncwarp();

    float c2[64];
    #pragma unroll
    for (int i = 0; i < 64; ++i) c2[i] = 0.0f;

    mb_wait(mb0, ph0); ph0 ^= 1;
    doChunk(SO_A0, SO_B0, c2);
    mb_wait(mb1, ph1); ph1 ^= 1;
    doChunk(SO_A1, SO_B1, c2);

    #pragma unroll
    for (int f = 0; f < 16; ++f) {
        int col = 8 * f + 2 * q;
        float2 b = *(float2*)(sBh2 + col);
        if (row0 < N) {
            float2 v; v.x = c2[4*f+0] + b.x; v.y = c2[4*f+1] + b.y;
            *(float2*)(outH + (size_t)row0 * Fdim + col) = v;
        }
        if (row1 < N) {
            float2 v; v.x = c2[4*f+2] + b.x; v.y = c2[4*f+3] + b.y;
            *(float2*)(outH + (size_t)row1 * Fdim + col) = v;
        }
    }
}

// ---------------- coordinate update -----------------------------------------
__global__ void x_kernel(const float* __restrict__ coord,
                         float* __restrict__ outX,
                         int n3, float C)
{
    int i = blockIdx.x * blockDim.x + threadIdx.x;
    if (i < n3) {
        int n = i / 3, d = i - n * 3;
        outX[i] = coord[i] + g_dx4[(size_t)n * 4 + d] * C;
    }
}

// ---------------- launch -----------------------------------------------------
extern "C" void kernel_launch(void* const* d_in, const int* in_sizes, int n_in,
                              void* d_out, int out_size)
{
    const float* node  = (const float*)d_in[0];
    const float* coord = (const float*)d_in[1];
    const int*   ei    = (const int*)d_in[2];
    const float* We1   = (const float*)d_in[3];
    const float* be1   = (const float*)d_in[4];
    const float* We2   = (const float*)d_in[5];
    const float* be2   = (const float*)d_in[6];
    const float* Wx    = (const float*)d_in[7];
    const float* bx    = (const float*)d_in[8];
    const float* Wh1   = (const float*)d_in[9];
    const float* bh1   = (const float*)d_in[10];
    const float* Wh2   = (const float*)d_in[11];
    const float* bh2   = (const float*)d_in[12];

    const int N = in_sizes[0] / Fdim;
    const int E = in_sizes[2] / 2;

    float* outH = (float*)d_out;
    float* outX = outH + (size_t)N * Fdim;

    cudaFuncSetAttribute(pq_kernel,   cudaFuncAttributeMaxDynamicSharedMemorySize, PQ_SMEM);
    cudaFuncSetAttribute(node_kernel, cudaFuncAttributeMaxDynamicSharedMemorySize, NODE_SMEM);

    prep_kernel<<<(65536 + 255) / 256, 256>>>(We1, Wh1, Wh2);
    prep2_kernel<<<(16641 + 255) / 256, 256>>>(We2, Wh1, Wx, be2, bx);
    {
        int n_mi = N * 128;
        zero_kernel<<<(n_mi + 255) / 256, 256>>>(node, n_mi, N);
    }
    hist_kernel<<<(E + 255) / 256, 256>>>(ei, E);
    {
        int grid = (N + ET2 - 1) / ET2;
        pq_kernel<<<grid, 512, PQ_SMEM>>>(be1, N);
    }
    scan_kernel<<<1, 1024>>>(N);
    place_kernel<<<(E + 255) / 256, 256>>>(ei, E);
    {
        int grid = (N * 32 + 255) / 256;
        agg_kernel<<<grid, 256>>>(coord, We1, N);
    }
    {
        int grid = (N + ET2 - 1) / ET2;
        node_kernel<<<grid, 512, NODE_SMEM>>>(bh1, bh2, outH, N);
    }
    {
        int n3 = N * 3;
        float C = 1.0f / (float)(N - 1);
        x_kernel<<<(n3 + 255) / 256, 256>>>(coord, outX, n3, C);
    }
}